// round 1
// baseline (speedup 1.0000x reference)
#include <cuda_runtime.h>

#define T_  64
#define B_  32
#define E_  512
#define H_  8
#define DH_ 64
#define F_  2048
#define TB_ (T_*B_)        // 2048
#define ROWS_ (T_*T_*B_)   // 131072

// ---------------- scratch (static __device__: no allocations allowed) --------
__device__ float g_qkv[TB_ * 3 * E_];   // (t*B+b, [q|k|v] 1536), q at 0, k at 512, v at 1024
__device__ float g_w[TB_ * H_ * T_];    // ((i*B+b)*H + h)*T + j
__device__ float g_attn[TB_ * E_];      // (i*B+b, h*64+d)
__device__ float g_ao[TB_ * E_];        // attn@out_w + out_b + x
__device__ float g_h[TB_ * E_];         // after LN1
__device__ float g_f1[TB_ * F_];        // relu(fc1)
__device__ float g_f2[TB_ * E_];        // fc2 + residual

// ---------------- generic fp32 SGEMM: 128x128 tile, K-step 8, 256 thr, 8x8 ----
// EPI: 0 = +bias; 1 = +bias,relu; 2 = +bias, +add
template<bool BTRANS, int EPI>
__global__ __launch_bounds__(256) void gemm_k(
    const float* __restrict__ A, const float* __restrict__ Bm,
    const float* __restrict__ bias, const float* __restrict__ add,
    float* __restrict__ C, int M, int N, int K)
{
    __shared__ float As[8][128];
    __shared__ float Bs[8][128];
    int tid = threadIdx.x;
    int tx = tid & 15, ty = tid >> 4;
    int m0 = blockIdx.y * 128;
    int n0 = blockIdx.x * 128;
    float acc[8][8] = {};

    int arow = tid >> 1;
    int acol = (tid & 1) * 4;
    const float* Ap = A + (size_t)(m0 + arow) * K + acol;

    int brow, bc;
    const float* Bp;
    if (BTRANS) { bc = tid >> 1; brow = (tid & 1) * 4; Bp = Bm + (size_t)(n0 + bc) * K + brow; }
    else        { brow = tid >> 5; bc = (tid & 31) * 4; Bp = Bm + (size_t)brow * N + n0 + bc; }

    for (int k0 = 0; k0 < K; k0 += 8) {
        float4 av = *(const float4*)(Ap + k0);
        float4 bv;
        if (BTRANS) bv = *(const float4*)(Bp + k0);
        else        bv = *(const float4*)(Bp + (size_t)k0 * N);
        As[acol+0][arow] = av.x; As[acol+1][arow] = av.y;
        As[acol+2][arow] = av.z; As[acol+3][arow] = av.w;
        if (BTRANS) { Bs[brow+0][bc] = bv.x; Bs[brow+1][bc] = bv.y;
                      Bs[brow+2][bc] = bv.z; Bs[brow+3][bc] = bv.w; }
        else        { *(float4*)&Bs[brow][bc] = bv; }
        __syncthreads();
        #pragma unroll
        for (int kk = 0; kk < 8; kk++) {
            float a[8], bb[8];
            #pragma unroll
            for (int i = 0; i < 8; i++) a[i]  = As[kk][ty*8 + i];
            #pragma unroll
            for (int j = 0; j < 8; j++) bb[j] = Bs[kk][tx*8 + j];
            #pragma unroll
            for (int i = 0; i < 8; i++)
                #pragma unroll
                for (int j = 0; j < 8; j++)
                    acc[i][j] = fmaf(a[i], bb[j], acc[i][j]);
        }
        __syncthreads();
    }
    #pragma unroll
    for (int i = 0; i < 8; i++) {
        int row = m0 + ty*8 + i;
        #pragma unroll
        for (int j = 0; j < 8; j++) {
            int col = n0 + tx*8 + j;
            float v = acc[i][j] + bias[col];
            if (EPI == 1) v = fmaxf(v, 0.f);
            if (EPI == 2) v += add[(size_t)row * N + col];
            C[(size_t)row * N + col] = v;
        }
    }
}

// ---------------- fused relation GEMM + attention-logit reduction ------------
// Block: 128 relation rows (n = (j*T+i)*B + b) x one head h.
// Computes ra (cols h*64..h*64+63 of rel_w) and rb (cols 512+h*64..),
// then w[i,j,b,h] = (1/64) * sum_d (q[i,b,h,d]+ra[d]) * (k[j,b,h,d]+rb[d]).
__global__ __launch_bounds__(256) void relw_kernel(
    const float* __restrict__ rel, const float* __restrict__ relw,
    const float* __restrict__ relb)
{
    __shared__ float As[8][128];
    __shared__ float Bs[8][128];
    int h  = blockIdx.x;            // fastest -> 8 CTAs share the same A rows (L2 reuse)
    int n0 = blockIdx.y * 128;
    int tid = threadIdx.x;
    int tx = tid & 15, ty = tid >> 4;
    float acc[8][8] = {};

    int arow = tid >> 1;
    int acol = (tid & 1) * 4;
    const float* Ap = rel + (size_t)(n0 + arow) * E_ + acol;

    int bk  = tid >> 5;
    int bc4 = (tid & 31) * 4;
    int bcol = (bc4 < 64) ? (h*64 + bc4) : (512 + h*64 + (bc4 - 64));
    const float* Bp = relw + (size_t)bk * (2*E_) + bcol;

    for (int k0 = 0; k0 < E_; k0 += 8) {
        float4 av = *(const float4*)(Ap + k0);
        float4 bv = *(const float4*)(Bp + (size_t)k0 * (2*E_));
        As[acol+0][arow] = av.x; As[acol+1][arow] = av.y;
        As[acol+2][arow] = av.z; As[acol+3][arow] = av.w;
        *(float4*)&Bs[bk][bc4] = bv;
        __syncthreads();
        #pragma unroll
        for (int kk = 0; kk < 8; kk++) {
            float a[8], bb[8];
            #pragma unroll
            for (int i = 0; i < 8; i++) a[i]  = As[kk][ty*8 + i];
            #pragma unroll
            for (int j = 0; j < 8; j++) bb[j] = Bs[kk][tx*8 + j];
            #pragma unroll
            for (int i = 0; i < 8; i++)
                #pragma unroll
                for (int j = 0; j < 8; j++)
                    acc[i][j] = fmaf(a[i], bb[j], acc[i][j]);
        }
        __syncthreads();
    }

    // Epilogue: tx<8 threads hold ra cols (d = tx*8+j), tx>=8 hold rb cols (same d).
    // Partner exchange via shfl_xor(8); reduce over the 8 tx in a group via 1,2,4.
    int dbase = (tx & 7) * 8;
    bool is_ra = (tx < 8);
    float addv[8];
    #pragma unroll
    for (int j = 0; j < 8; j++)
        addv[j] = is_ra ? relb[h*64 + dbase + j] : relb[512 + h*64 + dbase + j];

    #pragma unroll
    for (int i = 0; i < 8; i++) {
        int n  = n0 + ty*8 + i;
        int b  = n & 31;
        int ji = n >> 5;
        int ii = ji & 63;        // destination position i
        int jj = ji >> 6;        // source position j
        const float* qr = g_qkv + (size_t)(ii*B_ + b) * (3*E_) + h*64;
        const float* kr = g_qkv + (size_t)(jj*B_ + b) * (3*E_) + E_ + h*64;
        float part = 0.f;
        #pragma unroll
        for (int j = 0; j < 8; j++) {
            int d = dbase + j;
            float e  = acc[i][j] + addv[j] + (is_ra ? qr[d] : kr[d]);
            float eo = __shfl_xor_sync(0xffffffffu, e, 8);
            part += e * eo;
        }
        part += __shfl_xor_sync(0xffffffffu, part, 1);
        part += __shfl_xor_sync(0xffffffffu, part, 2);
        part += __shfl_xor_sync(0xffffffffu, part, 4);
        if (tx == 0)
            g_w[((size_t)(ii*B_ + b) * H_ + h) * T_ + jj] = part * 0.015625f; // s^2 = 1/64
    }
}

// ---------------- softmax over j + attn = p @ v ------------------------------
__global__ __launch_bounds__(256) void softmax_attn_kernel()
{
    int ib = blockIdx.x;          // i*B+b
    int b  = ib & 31;
    __shared__ float p[H_][T_];
    int t = threadIdx.x;
    int w = t >> 5, l = t & 31;   // warp w == head w (8 warps)

    float v0 = g_w[((size_t)ib*H_ + w)*T_ + l];
    float v1 = g_w[((size_t)ib*H_ + w)*T_ + l + 32];
    float mx = fmaxf(v0, v1);
    #pragma unroll
    for (int o = 16; o; o >>= 1) mx = fmaxf(mx, __shfl_xor_sync(~0u, mx, o));
    float e0 = expf(v0 - mx), e1 = expf(v1 - mx);
    float s = e0 + e1;
    #pragma unroll
    for (int o = 16; o; o >>= 1) s += __shfl_xor_sync(~0u, s, o);
    float inv = 1.0f / s;
    p[w][l]      = e0 * inv;
    p[w][l + 32] = e1 * inv;
    __syncthreads();

    #pragma unroll
    for (int c0 = 0; c0 < E_; c0 += 256) {
        int c = c0 + t;
        int h = c >> 6, d = c & 63;
        float acc = 0.f;
        #pragma unroll 8
        for (int j = 0; j < T_; j++)
            acc += p[h][j] * g_qkv[(size_t)(j*B_ + b) * (3*E_) + 2*E_ + h*64 + d];
        g_attn[(size_t)ib * E_ + c] = acc;
    }
}

// ---------------- layernorm over last dim (512) ------------------------------
__global__ __launch_bounds__(256) void ln_kernel(
    const float* __restrict__ in, const float* __restrict__ g,
    const float* __restrict__ b, float* __restrict__ out)
{
    int row = blockIdx.x;
    const float* r = in + (size_t)row * E_;
    int t = threadIdx.x;
    float v0 = r[t], v1 = r[t + 256];
    float s = v0 + v1, sq = v0*v0 + v1*v1;
    #pragma unroll
    for (int o = 16; o; o >>= 1) {
        s  += __shfl_xor_sync(~0u, s,  o);
        sq += __shfl_xor_sync(~0u, sq, o);
    }
    __shared__ float ss[8], ssq[8];
    int w = t >> 5, l = t & 31;
    if (l == 0) { ss[w] = s; ssq[w] = sq; }
    __syncthreads();
    if (w == 0) {
        s  = (l < 8) ? ss[l]  : 0.f;
        sq = (l < 8) ? ssq[l] : 0.f;
        #pragma unroll
        for (int o = 4; o; o >>= 1) {
            s  += __shfl_xor_sync(~0u, s,  o);
            sq += __shfl_xor_sync(~0u, sq, o);
        }
        if (l == 0) { ss[0] = s; ssq[0] = sq; }
    }
    __syncthreads();
    float mu   = ss[0]  * (1.f / E_);
    float var  = ssq[0] * (1.f / E_) - mu * mu;
    float rstd = rsqrtf(var + 1e-5f);
    out[(size_t)row*E_ + t]       = (v0 - mu) * rstd * g[t]       + b[t];
    out[(size_t)row*E_ + t + 256] = (v1 - mu) * rstd * g[t + 256] + b[t + 256];
}

// ---------------- launch ------------------------------------------------------
extern "C" void kernel_launch(void* const* d_in, const int* in_sizes, int n_in,
                              void* d_out, int out_size)
{
    const float* x        = (const float*)d_in[0];
    const float* relation = (const float*)d_in[1];
    const float* in_w     = (const float*)d_in[2];
    const float* in_b     = (const float*)d_in[3];
    const float* rel_w    = (const float*)d_in[4];
    const float* rel_b    = (const float*)d_in[5];
    const float* out_w    = (const float*)d_in[6];
    const float* out_b    = (const float*)d_in[7];
    const float* fc1_w    = (const float*)d_in[8];
    const float* fc1_b    = (const float*)d_in[9];
    const float* fc2_w    = (const float*)d_in[10];
    const float* fc2_b    = (const float*)d_in[11];
    const float* ln1_g    = (const float*)d_in[12];
    const float* ln1_b    = (const float*)d_in[13];
    const float* ln2_g    = (const float*)d_in[14];
    const float* ln2_b    = (const float*)d_in[15];
    float* out = (float*)d_out;

    static float *p_qkv = nullptr, *p_attn, *p_ao, *p_h, *p_f1, *p_f2;
    if (!p_qkv) {  // resolved on the (uncaptured) correctness call, reused thereafter
        cudaGetSymbolAddress((void**)&p_qkv,  g_qkv);
        cudaGetSymbolAddress((void**)&p_attn, g_attn);
        cudaGetSymbolAddress((void**)&p_ao,   g_ao);
        cudaGetSymbolAddress((void**)&p_h,    g_h);
        cudaGetSymbolAddress((void**)&p_f1,   g_f1);
        cudaGetSymbolAddress((void**)&p_f2,   g_f2);
    }

    dim3 blk(256);

    // 1. qkv = x @ in_w^T + in_b          (2048 x 1536, K=512)
    gemm_k<true, 0><<<dim3(1536/128, TB_/128), blk>>>(x, in_w, in_b, nullptr, p_qkv, TB_, 3*E_, E_);

    // 2. fused relation GEMM + logits w   (131072 x 128-per-head, K=512) -- the 137 GF kernel
    relw_kernel<<<dim3(H_, ROWS_/128), blk>>>(relation, rel_w, rel_b);

    // 3. softmax over j + attn = p @ v
    softmax_attn_kernel<<<TB_, 256>>>();

    // 4. out proj + out_b + residual x
    gemm_k<false, 2><<<dim3(E_/128, TB_/128), blk>>>(p_attn, out_w, out_b, x, p_ao, TB_, E_, E_);

    // 5. LN1 -> h
    ln_kernel<<<TB_, 256>>>(p_ao, ln1_g, ln1_b, p_h);

    // 6. fc1 + relu
    gemm_k<false, 1><<<dim3(F_/128, TB_/128), blk>>>(p_h, fc1_w, fc1_b, nullptr, p_f1, TB_, F_, E_);

    // 7. fc2 + fc2_b + residual h
    gemm_k<false, 2><<<dim3(E_/128, TB_/128), blk>>>(p_f1, fc2_w, fc2_b, p_h, p_f2, TB_, E_, F_);

    // 8. LN2 -> out
    ln_kernel<<<TB_, 256>>>(p_f2, ln2_g, ln2_b, out);
}

// round 2
// speedup vs baseline: 2.5879x; 2.5879x over previous
#include <cuda_runtime.h>
#include <cuda_bf16.h>
#include <cstdint>

#define T_  64
#define B_  32
#define E_  512
#define H_  8
#define F_  2048
#define TB_ (T_*B_)        // 2048
#define ROWS_ (T_*T_*B_)   // 131072

// ---------------- scratch ----------------------------------------------------
__device__ float g_qkv[TB_ * 3 * E_];   // (t*B+b, [q|k|v])
__device__ float g_w[TB_ * H_ * T_];    // ((i*B+b)*H + h)*T + j
__device__ float g_attn[TB_ * E_];
__device__ float g_ao[TB_ * E_];
__device__ float g_h[TB_ * E_];
__device__ float g_f1[TB_ * F_];
__device__ float g_f2[TB_ * E_];

// ---------------- mma helpers -------------------------------------------------
__device__ __forceinline__ uint32_t smem_u32(const void* p) {
    return (uint32_t)__cvta_generic_to_shared(p);
}
__device__ __forceinline__ void ldsm_x4(uint32_t& r0, uint32_t& r1, uint32_t& r2, uint32_t& r3, uint32_t a) {
    asm volatile("ldmatrix.sync.aligned.m8n8.x4.shared.b16 {%0,%1,%2,%3},[%4];"
                 : "=r"(r0), "=r"(r1), "=r"(r2), "=r"(r3) : "r"(a));
}
__device__ __forceinline__ void ldsm_x4_t(uint32_t& r0, uint32_t& r1, uint32_t& r2, uint32_t& r3, uint32_t a) {
    asm volatile("ldmatrix.sync.aligned.m8n8.x4.trans.shared.b16 {%0,%1,%2,%3},[%4];"
                 : "=r"(r0), "=r"(r1), "=r"(r2), "=r"(r3) : "r"(a));
}
__device__ __forceinline__ void mma16816(float* c, const uint32_t* a, const uint32_t* b) {
    asm volatile("mma.sync.aligned.m16n8k16.row.col.f32.bf16.bf16.f32 "
                 "{%0,%1,%2,%3},{%4,%5,%6,%7},{%8,%9},{%0,%1,%2,%3};"
                 : "+f"(c[0]), "+f"(c[1]), "+f"(c[2]), "+f"(c[3])
                 : "r"(a[0]), "r"(a[1]), "r"(a[2]), "r"(a[3]), "r"(b[0]), "r"(b[1]));
}
__device__ __forceinline__ uint32_t f2bf2(float x, float y) {
    __nv_bfloat162 t = __floats2bfloat162_rn(x, y);
    return *reinterpret_cast<uint32_t*>(&t);
}

// ---------------- fused relation GEMM (bf16 tensor core) + logits -------------
// Block: 128 relation rows x one head h. Bs cols interleaved: col 2d = ra_d,
// col 2d+1 = rb_d -> each thread's (c0,c1) C-fragment pair is an (ra,rb) pair.
// w[i,j,b,h] = (1/64) * sum_d (q+ra)(k+rb).
__global__ void __launch_bounds__(256, 1) relw_mma(
    const float* __restrict__ rel, const float* __restrict__ relw,
    const float* __restrict__ relb)
{
    extern __shared__ char smem[];
    // As: 2 bufs of 128x64 bf16 (16KB each), swizzled; Bs: 2 bufs of 64x128 bf16
    const uint32_t AsBase = smem_u32(smem);
    const uint32_t BsBase = AsBase + 32768;
    float* red = (float*)smem;   // epilogue alias (after barrier)

    const int h   = blockIdx.x;
    const int n0  = blockIdx.y * 128;
    const int tid = threadIdx.x;
    const int lane = tid & 31, warp = tid >> 5;
    const int warp_m = warp >> 1, warp_n = warp & 1;

    float acc[2][8][4];
    #pragma unroll
    for (int i = 0; i < 2; i++)
        #pragma unroll
        for (int j = 0; j < 8; j++)
            #pragma unroll
            for (int k = 0; k < 4; k++) acc[i][j][k] = 0.f;

    const float* Arel = rel + (size_t)n0 * E_;
    const int kr = tid >> 2;       // B stage row 0..63
    const int dg = tid & 3;        // B stage d-group (16 d's each)

    float4 ar[8], rar[4], rbr[4];

    // ---- stage-0 global loads
    {
        #pragma unroll
        for (int it = 0; it < 8; it++) {
            int idx = it * 1024 + tid * 4;
            ar[it] = *(const float4*)(Arel + (size_t)(idx >> 6) * E_ + (idx & 63));
        }
        const float* wra = relw + (size_t)kr * (2*E_) + h*64 + dg*16;
        #pragma unroll
        for (int i = 0; i < 4; i++) { rar[i] = ((const float4*)wra)[i]; rbr[i] = ((const float4*)(wra + E_))[i]; }
    }
    // ---- store stage 0
    {
        char* Ab = smem;
        #pragma unroll
        for (int it = 0; it < 8; it++) {
            int idx = it * 1024 + tid * 4;
            int row = idx >> 6, col = idx & 63;
            uint2 v = make_uint2(f2bf2(ar[it].x, ar[it].y), f2bf2(ar[it].z, ar[it].w));
            *(uint2*)(Ab + row*128 + ((((col>>3) ^ (row&7)) << 4) | ((col&7) << 1))) = v;
        }
        char* Bb = smem + 32768;
        #pragma unroll
        for (int cj = 0; cj < 4; cj++) {
            const float* ra4 = (const float*)&rar[cj];
            const float* rb4 = (const float*)&rbr[cj];
            uint4 v = make_uint4(f2bf2(ra4[0], rb4[0]), f2bf2(ra4[1], rb4[1]),
                                 f2bf2(ra4[2], rb4[2]), f2bf2(ra4[3], rb4[3]));
            int chunk = (dg << 2) | cj;
            *(uint4*)(Bb + kr*256 + ((chunk ^ (kr&7)) << 4)) = v;
        }
    }
    __syncthreads();

    #pragma unroll
    for (int s = 0; s < 8; s++) {
        // prefetch next stage into regs
        if (s < 7) {
            int k0 = (s + 1) * 64;
            #pragma unroll
            for (int it = 0; it < 8; it++) {
                int idx = it * 1024 + tid * 4;
                ar[it] = *(const float4*)(Arel + (size_t)(idx >> 6) * E_ + k0 + (idx & 63));
            }
            const float* wra = relw + (size_t)(k0 + kr) * (2*E_) + h*64 + dg*16;
            #pragma unroll
            for (int i = 0; i < 4; i++) { rar[i] = ((const float4*)wra)[i]; rbr[i] = ((const float4*)(wra + E_))[i]; }
        }
        // mma on current buffer
        const uint32_t Ab = AsBase + (s & 1) * 16384;
        const uint32_t Bb = BsBase + (s & 1) * 16384;
        #pragma unroll
        for (int ks = 0; ks < 4; ks++) {
            uint32_t a[2][4];
            #pragma unroll
            for (int mi = 0; mi < 2; mi++) {
                int r  = warp_m*32 + mi*16 + (lane & 15);
                int kc = ks*16 + ((lane >> 4) << 3);
                ldsm_x4(a[mi][0], a[mi][1], a[mi][2], a[mi][3],
                        Ab + r*128 + ((((kc >> 3) ^ (r & 7)) << 4)));
            }
            uint32_t b[8][2];
            #pragma unroll
            for (int g = 0; g < 4; g++) {
                int krow = ks*16 + (lane & 15);
                int ncol = warp_n*64 + g*16 + ((lane >> 4) << 3);
                ldsm_x4_t(b[2*g][0], b[2*g][1], b[2*g+1][0], b[2*g+1][1],
                          Bb + krow*256 + ((((ncol >> 3) ^ (krow & 7)) << 4)));
            }
            #pragma unroll
            for (int mi = 0; mi < 2; mi++)
                #pragma unroll
                for (int nf = 0; nf < 8; nf++)
                    mma16816(acc[mi][nf], a[mi], b[nf]);
        }
        // store prefetched stage
        if (s < 7) {
            __syncthreads();
            char* Abc = smem + ((s + 1) & 1) * 16384;
            #pragma unroll
            for (int it = 0; it < 8; it++) {
                int idx = it * 1024 + tid * 4;
                int row = idx >> 6, col = idx & 63;
                uint2 v = make_uint2(f2bf2(ar[it].x, ar[it].y), f2bf2(ar[it].z, ar[it].w));
                *(uint2*)(Abc + row*128 + ((((col>>3) ^ (row&7)) << 4) | ((col&7) << 1))) = v;
            }
            char* Bbc = smem + 32768 + ((s + 1) & 1) * 16384;
            #pragma unroll
            for (int cj = 0; cj < 4; cj++) {
                const float* ra4 = (const float*)&rar[cj];
                const float* rb4 = (const float*)&rbr[cj];
                uint4 v = make_uint4(f2bf2(ra4[0], rb4[0]), f2bf2(ra4[1], rb4[1]),
                                     f2bf2(ra4[2], rb4[2]), f2bf2(ra4[3], rb4[3]));
                int chunk = (dg << 2) | cj;
                *(uint4*)(Bbc + kr*256 + ((chunk ^ (kr&7)) << 4)) = v;
            }
            __syncthreads();
        }
    }

    // ---- fused epilogue: e_ra = c0 + bias + q ; e_rb = c1 + bias + k ; dot over d
    const int tig = lane & 3, grp = lane >> 2;
    float part[2][2] = {{0.f, 0.f}, {0.f, 0.f}};
    #pragma unroll
    for (int nf = 0; nf < 8; nf++) {
        int d = warp_n*32 + nf*4 + tig;
        float bra = relb[h*64 + d];
        float brb = relb[E_ + h*64 + d];
        #pragma unroll
        for (int mi = 0; mi < 2; mi++)
            #pragma unroll
            for (int hf = 0; hf < 2; hf++) {
                int r  = warp_m*32 + mi*16 + grp + hf*8;
                int n  = n0 + r;
                int b  = n & 31;
                int ji = n >> 5;
                int ii = ji & 63, jj = ji >> 6;
                float q = g_qkv[(size_t)(ii*B_ + b) * (3*E_) + h*64 + d];
                float k = g_qkv[(size_t)(jj*B_ + b) * (3*E_) + E_ + h*64 + d];
                part[mi][hf] += (acc[mi][nf][hf*2+0] + bra + q) * (acc[mi][nf][hf*2+1] + brb + k);
            }
    }
    #pragma unroll
    for (int mi = 0; mi < 2; mi++)
        #pragma unroll
        for (int hf = 0; hf < 2; hf++) {
            float v = part[mi][hf];
            v += __shfl_xor_sync(~0u, v, 1);
            v += __shfl_xor_sync(~0u, v, 2);
            part[mi][hf] = v;
        }
    __syncthreads();   // everyone done reading smem tiles; safe to alias red
    if (tig == 0) {
        #pragma unroll
        for (int mi = 0; mi < 2; mi++)
            #pragma unroll
            for (int hf = 0; hf < 2; hf++) {
                int r = warp_m*32 + mi*16 + grp + hf*8;
                red[r*2 + warp_n] = part[mi][hf];
            }
    }
    __syncthreads();
    if (tid < 128) {
        int n  = n0 + tid;
        int b  = n & 31;
        int ji = n >> 5;
        int ii = ji & 63, jj = ji >> 6;
        g_w[((size_t)(ii*B_ + b) * H_ + h) * T_ + jj] =
            (red[tid*2] + red[tid*2 + 1]) * 0.015625f;
    }
}

// ---------------- fp32 SGEMM 128x128 (BTRANS path for qkv) --------------------
template<bool BTRANS, int EPI>
__global__ __launch_bounds__(256) void gemm_k(
    const float* __restrict__ A, const float* __restrict__ Bm,
    const float* __restrict__ bias, const float* __restrict__ add,
    float* __restrict__ C, int M, int N, int K)
{
    __shared__ float As[8][128];
    __shared__ float Bs[8][128];
    int tid = threadIdx.x;
    int tx = tid & 15, ty = tid >> 4;
    int m0 = blockIdx.y * 128;
    int n0 = blockIdx.x * 128;
    float acc[8][8] = {};

    int arow = tid >> 1;
    int acol = (tid & 1) * 4;
    const float* Ap = A + (size_t)(m0 + arow) * K + acol;

    int brow, bc;
    const float* Bp;
    if (BTRANS) { bc = tid >> 1; brow = (tid & 1) * 4; Bp = Bm + (size_t)(n0 + bc) * K + brow; }
    else        { brow = tid >> 5; bc = (tid & 31) * 4; Bp = Bm + (size_t)brow * N + n0 + bc; }

    for (int k0 = 0; k0 < K; k0 += 8) {
        float4 av = *(const float4*)(Ap + k0);
        float4 bv;
        if (BTRANS) bv = *(const float4*)(Bp + k0);
        else        bv = *(const float4*)(Bp + (size_t)k0 * N);
        As[acol+0][arow] = av.x; As[acol+1][arow] = av.y;
        As[acol+2][arow] = av.z; As[acol+3][arow] = av.w;
        if (BTRANS) { Bs[brow+0][bc] = bv.x; Bs[brow+1][bc] = bv.y;
                      Bs[brow+2][bc] = bv.z; Bs[brow+3][bc] = bv.w; }
        else        { *(float4*)&Bs[brow][bc] = bv; }
        __syncthreads();
        #pragma unroll
        for (int kk = 0; kk < 8; kk++) {
            float a[8], bb[8];
            #pragma unroll
            for (int i = 0; i < 8; i++) a[i]  = As[kk][ty*8 + i];
            #pragma unroll
            for (int j = 0; j < 8; j++) bb[j] = Bs[kk][tx*8 + j];
            #pragma unroll
            for (int i = 0; i < 8; i++)
                #pragma unroll
                for (int j = 0; j < 8; j++)
                    acc[i][j] = fmaf(a[i], bb[j], acc[i][j]);
        }
        __syncthreads();
    }
    #pragma unroll
    for (int i = 0; i < 8; i++) {
        int row = m0 + ty*8 + i;
        #pragma unroll
        for (int j = 0; j < 8; j++) {
            int col = n0 + tx*8 + j;
            float v = acc[i][j] + bias[col];
            if (EPI == 1) v = fmaxf(v, 0.f);
            if (EPI == 2) v += add[(size_t)row * N + col];
            C[(size_t)row * N + col] = v;
        }
    }
}

// ---------------- fp32 SGEMM 128x64 (better occupancy for N<=512) -------------
template<int EPI>
__global__ __launch_bounds__(256) void gemm_n64(
    const float* __restrict__ A, const float* __restrict__ Bm,
    const float* __restrict__ bias, const float* __restrict__ add,
    float* __restrict__ C, int M, int N, int K)
{
    __shared__ float As[8][128];
    __shared__ float Bs[8][64];
    int tid = threadIdx.x;
    int tx = tid & 7, ty = tid >> 3;     // 8 x 32
    int m0 = blockIdx.y * 128;
    int n0 = blockIdx.x * 64;
    float acc[4][8] = {};

    int arow = tid >> 1;
    int acol = (tid & 1) * 4;
    const float* Ap = A + (size_t)(m0 + arow) * K + acol;
    int brow = tid >> 5, bcol = (tid & 31) * 2;
    const float* Bp = Bm + (size_t)brow * N + n0 + bcol;

    for (int k0 = 0; k0 < K; k0 += 8) {
        float4 av = *(const float4*)(Ap + k0);
        float2 bv = *(const float2*)(Bp + (size_t)k0 * N);
        As[acol+0][arow] = av.x; As[acol+1][arow] = av.y;
        As[acol+2][arow] = av.z; As[acol+3][arow] = av.w;
        *(float2*)&Bs[brow][bcol] = bv;
        __syncthreads();
        #pragma unroll
        for (int kk = 0; kk < 8; kk++) {
            float a[4], bb[8];
            #pragma unroll
            for (int i = 0; i < 4; i++) a[i]  = As[kk][ty*4 + i];
            #pragma unroll
            for (int j = 0; j < 8; j++) bb[j] = Bs[kk][tx*8 + j];
            #pragma unroll
            for (int i = 0; i < 4; i++)
                #pragma unroll
                for (int j = 0; j < 8; j++)
                    acc[i][j] = fmaf(a[i], bb[j], acc[i][j]);
        }
        __syncthreads();
    }
    #pragma unroll
    for (int i = 0; i < 4; i++) {
        int row = m0 + ty*4 + i;
        #pragma unroll
        for (int j = 0; j < 8; j++) {
            int col = n0 + tx*8 + j;
            float v = acc[i][j] + bias[col];
            if (EPI == 1) v = fmaxf(v, 0.f);
            if (EPI == 2) v += add[(size_t)row * N + col];
            C[(size_t)row * N + col] = v;
        }
    }
}

// ---------------- softmax over j + attn = p @ v ------------------------------
__global__ __launch_bounds__(256) void softmax_attn_kernel()
{
    int ib = blockIdx.x;
    int b  = ib & 31;
    __shared__ float p[H_][T_];
    int t = threadIdx.x;
    int w = t >> 5, l = t & 31;

    float v0 = g_w[((size_t)ib*H_ + w)*T_ + l];
    float v1 = g_w[((size_t)ib*H_ + w)*T_ + l + 32];
    float mx = fmaxf(v0, v1);
    #pragma unroll
    for (int o = 16; o; o >>= 1) mx = fmaxf(mx, __shfl_xor_sync(~0u, mx, o));
    float e0 = expf(v0 - mx), e1 = expf(v1 - mx);
    float s = e0 + e1;
    #pragma unroll
    for (int o = 16; o; o >>= 1) s += __shfl_xor_sync(~0u, s, o);
    float inv = 1.0f / s;
    p[w][l]      = e0 * inv;
    p[w][l + 32] = e1 * inv;
    __syncthreads();

    #pragma unroll
    for (int c0 = 0; c0 < E_; c0 += 256) {
        int c = c0 + t;
        int hh = c >> 6, d = c & 63;
        float acc = 0.f;
        #pragma unroll 8
        for (int j = 0; j < T_; j++)
            acc += p[hh][j] * g_qkv[(size_t)(j*B_ + b) * (3*E_) + 2*E_ + hh*64 + d];
        g_attn[(size_t)ib * E_ + c] = acc;
    }
}

// ---------------- layernorm ----------------------------------------------------
__global__ __launch_bounds__(256) void ln_kernel(
    const float* __restrict__ in, const float* __restrict__ g,
    const float* __restrict__ b, float* __restrict__ out)
{
    int row = blockIdx.x;
    const float* r = in + (size_t)row * E_;
    int t = threadIdx.x;
    float v0 = r[t], v1 = r[t + 256];
    float s = v0 + v1, sq = v0*v0 + v1*v1;
    #pragma unroll
    for (int o = 16; o; o >>= 1) {
        s  += __shfl_xor_sync(~0u, s,  o);
        sq += __shfl_xor_sync(~0u, sq, o);
    }
    __shared__ float ss[8], ssq[8];
    int w = t >> 5, l = t & 31;
    if (l == 0) { ss[w] = s; ssq[w] = sq; }
    __syncthreads();
    if (w == 0) {
        s  = (l < 8) ? ss[l]  : 0.f;
        sq = (l < 8) ? ssq[l] : 0.f;
        #pragma unroll
        for (int o = 4; o; o >>= 1) {
            s  += __shfl_xor_sync(~0u, s,  o);
            sq += __shfl_xor_sync(~0u, sq, o);
        }
        if (l == 0) { ss[0] = s; ssq[0] = sq; }
    }
    __syncthreads();
    float mu   = ss[0]  * (1.f / E_);
    float var  = ssq[0] * (1.f / E_) - mu * mu;
    float rstd = rsqrtf(var + 1e-5f);
    out[(size_t)row*E_ + t]       = (v0 - mu) * rstd * g[t]       + b[t];
    out[(size_t)row*E_ + t + 256] = (v1 - mu) * rstd * g[t + 256] + b[t + 256];
}

// ---------------- launch --------------------------------------------------------
extern "C" void kernel_launch(void* const* d_in, const int* in_sizes, int n_in,
                              void* d_out, int out_size)
{
    const float* x        = (const float*)d_in[0];
    const float* relation = (const float*)d_in[1];
    const float* in_w     = (const float*)d_in[2];
    const float* in_b     = (const float*)d_in[3];
    const float* rel_w    = (const float*)d_in[4];
    const float* rel_b    = (const float*)d_in[5];
    const float* out_w    = (const float*)d_in[6];
    const float* out_b    = (const float*)d_in[7];
    const float* fc1_w    = (const float*)d_in[8];
    const float* fc1_b    = (const float*)d_in[9];
    const float* fc2_w    = (const float*)d_in[10];
    const float* fc2_b    = (const float*)d_in[11];
    const float* ln1_g    = (const float*)d_in[12];
    const float* ln1_b    = (const float*)d_in[13];
    const float* ln2_g    = (const float*)d_in[14];
    const float* ln2_b    = (const float*)d_in[15];
    float* out = (float*)d_out;

    static float *p_qkv = nullptr, *p_attn, *p_ao, *p_h, *p_f1, *p_f2;
    if (!p_qkv) {
        cudaGetSymbolAddress((void**)&p_qkv,  g_qkv);
        cudaGetSymbolAddress((void**)&p_attn, g_attn);
        cudaGetSymbolAddress((void**)&p_ao,   g_ao);
        cudaGetSymbolAddress((void**)&p_h,    g_h);
        cudaGetSymbolAddress((void**)&p_f1,   g_f1);
        cudaGetSymbolAddress((void**)&p_f2,   g_f2);
        cudaFuncSetAttribute(relw_mma, cudaFuncAttributeMaxDynamicSharedMemorySize, 65536);
    }

    dim3 blk(256);

    // 1. qkv = x @ in_w^T + in_b
    gemm_k<true, 0><<<dim3(1536/128, TB_/128), blk>>>(x, in_w, in_b, nullptr, p_qkv, TB_, 3*E_, E_);

    // 2. fused relation GEMM (bf16 tensor core) + logits
    relw_mma<<<dim3(H_, ROWS_/128), blk, 65536>>>(relation, rel_w, rel_b);

    // 3. softmax + attn
    softmax_attn_kernel<<<TB_, 256>>>();

    // 4. out proj + residual
    gemm_n64<2><<<dim3(E_/64, TB_/128), blk>>>(p_attn, out_w, out_b, x, p_ao, TB_, E_, E_);

    // 5. LN1
    ln_kernel<<<TB_, 256>>>(p_ao, ln1_g, ln1_b, p_h);

    // 6. fc1 + relu
    gemm_n64<1><<<dim3(F_/64, TB_/128), blk>>>(p_h, fc1_w, fc1_b, nullptr, p_f1, TB_, F_, E_);

    // 7. fc2 + residual h
    gemm_n64<2><<<dim3(E_/64, TB_/128), blk>>>(p_f1, fc2_w, fc2_b, p_h, p_f2, TB_, E_, F_);

    // 8. LN2 -> out
    ln_kernel<<<TB_, 256>>>(p_f2, ln2_g, ln2_b, out);
}

// round 3
// speedup vs baseline: 3.8150x; 1.4741x over previous
#include <cuda_runtime.h>
#include <cuda_bf16.h>
#include <cstdint>

#define T_  64
#define B_  32
#define E_  512
#define H_  8
#define F_  2048
#define TB_ (T_*B_)        // 2048
#define ROWS_ (T_*T_*B_)   // 131072

// ---------------- scratch ----------------------------------------------------
__device__ float g_qkv[TB_ * 3 * E_];
__device__ float g_w[TB_ * H_ * T_];
__device__ float g_attn[TB_ * E_];
__device__ float g_ao[TB_ * E_];
__device__ float g_h[TB_ * E_];
__device__ float g_f1[TB_ * F_];
__device__ float g_f2[TB_ * E_];

// ---------------- mma helpers -------------------------------------------------
__device__ __forceinline__ uint32_t smem_u32(const void* p) {
    return (uint32_t)__cvta_generic_to_shared(p);
}
__device__ __forceinline__ void ldsm_x4(uint32_t& r0, uint32_t& r1, uint32_t& r2, uint32_t& r3, uint32_t a) {
    asm volatile("ldmatrix.sync.aligned.m8n8.x4.shared.b16 {%0,%1,%2,%3},[%4];"
                 : "=r"(r0), "=r"(r1), "=r"(r2), "=r"(r3) : "r"(a));
}
__device__ __forceinline__ void ldsm_x4_t(uint32_t& r0, uint32_t& r1, uint32_t& r2, uint32_t& r3, uint32_t a) {
    asm volatile("ldmatrix.sync.aligned.m8n8.x4.trans.shared.b16 {%0,%1,%2,%3},[%4];"
                 : "=r"(r0), "=r"(r1), "=r"(r2), "=r"(r3) : "r"(a));
}
__device__ __forceinline__ void mma16816(float* c, const uint32_t* a, const uint32_t* b) {
    asm volatile("mma.sync.aligned.m16n8k16.row.col.f32.bf16.bf16.f32 "
                 "{%0,%1,%2,%3},{%4,%5,%6,%7},{%8,%9},{%0,%1,%2,%3};"
                 : "+f"(c[0]), "+f"(c[1]), "+f"(c[2]), "+f"(c[3])
                 : "r"(a[0]), "r"(a[1]), "r"(a[2]), "r"(a[3]), "r"(b[0]), "r"(b[1]));
}
__device__ __forceinline__ void mma_tf32(float* c, const float* a, const float* b) {
    asm volatile("mma.sync.aligned.m16n8k8.row.col.f32.tf32.tf32.f32 "
                 "{%0,%1,%2,%3},{%4,%5,%6,%7},{%8,%9},{%0,%1,%2,%3};"
                 : "+f"(c[0]), "+f"(c[1]), "+f"(c[2]), "+f"(c[3])
                 : "r"(__float_as_uint(a[0])), "r"(__float_as_uint(a[1])),
                   "r"(__float_as_uint(a[2])), "r"(__float_as_uint(a[3])),
                   "r"(__float_as_uint(b[0])), "r"(__float_as_uint(b[1])));
}
__device__ __forceinline__ uint32_t f2bf2(float x, float y) {
    __nv_bfloat162 t = __floats2bfloat162_rn(x, y);
    return *reinterpret_cast<uint32_t*>(&t);
}
__device__ __forceinline__ float to_tf32(float x) {
    float y;
    asm("cvt.rna.tf32.f32 %0, %1;" : "=f"(y) : "f"(x));
    return y;
}
__device__ __forceinline__ float4 to_tf32_4(float4 v) {
    return make_float4(to_tf32(v.x), to_tf32(v.y), to_tf32(v.z), to_tf32(v.w));
}

// ---------------- tf32 GEMM: 128x128 tile, K-stage 32, padded-scalar smem -----
// BTRANS: B is [N,K] row-major (qkv). else: B is [K,N] row-major.
// EPI: 0 = +bias; 1 = +bias,relu; 2 = +bias,+add
#define PA_ 36
#define PB_ 136
template<bool BTRANS, int EPI>
__global__ __launch_bounds__(256) void gemm_tf32(
    const float* __restrict__ A, const float* __restrict__ Bm,
    const float* __restrict__ bias, const float* __restrict__ add,
    float* __restrict__ C, int M, int N, int K)
{
    extern __shared__ float sm[];
    const int AW = 128 * PA_;                       // 4608 words per A buf
    const int BW = BTRANS ? 128 * PA_ : 32 * PB_;   // per B buf
    float* Asm[2] = { sm, sm + AW };
    float* Bsm[2] = { sm + 2*AW, sm + 2*AW + BW };

    const int tid = threadIdx.x;
    const int lane = tid & 31, warp = tid >> 5;
    const int wm = warp >> 1, wn = warp & 1;        // warp tile 32(m) x 64(n)
    const int grp = lane >> 2, tig = lane & 3;
    const int m0 = blockIdx.y * 128;
    const int n0 = blockIdx.x * 128;

    float acc[2][8][4];
    #pragma unroll
    for (int i = 0; i < 2; i++)
        #pragma unroll
        for (int j = 0; j < 8; j++)
            #pragma unroll
            for (int k = 0; k < 4; k++) acc[i][j][k] = 0.f;

    const int S = K >> 5;
    float4 pa[4], pb[4];

    // ---- load + store stage 0
    #pragma unroll
    for (int it = 0; it < 4; it++) {
        int idx = it * 1024 + tid * 4;
        pa[it] = *(const float4*)(A + (size_t)(m0 + (idx >> 5)) * K + (idx & 31));
        if (BTRANS) pb[it] = *(const float4*)(Bm + (size_t)(n0 + (idx >> 5)) * K + (idx & 31));
        else        pb[it] = *(const float4*)(Bm + (size_t)(idx >> 7) * N + n0 + (idx & 127));
    }
    #pragma unroll
    for (int it = 0; it < 4; it++) {
        int idx = it * 1024 + tid * 4;
        *(float4*)&Asm[0][(idx >> 5) * PA_ + (idx & 31)] = to_tf32_4(pa[it]);
        if (BTRANS) *(float4*)&Bsm[0][(idx >> 5) * PA_ + (idx & 31)] = to_tf32_4(pb[it]);
        else        *(float4*)&Bsm[0][(idx >> 7) * PB_ + (idx & 127)] = to_tf32_4(pb[it]);
    }
    __syncthreads();

    for (int s = 0; s < S; s++) {
        if (s < S - 1) {
            int k0 = (s + 1) * 32;
            #pragma unroll
            for (int it = 0; it < 4; it++) {
                int idx = it * 1024 + tid * 4;
                pa[it] = *(const float4*)(A + (size_t)(m0 + (idx >> 5)) * K + k0 + (idx & 31));
                if (BTRANS) pb[it] = *(const float4*)(Bm + (size_t)(n0 + (idx >> 5)) * K + k0 + (idx & 31));
                else        pb[it] = *(const float4*)(Bm + (size_t)(k0 + (idx >> 7)) * N + n0 + (idx & 127));
            }
        }
        const float* Ab = Asm[s & 1];
        const float* Bb = Bsm[s & 1];
        #pragma unroll
        for (int ks = 0; ks < 4; ks++) {
            float a[2][4];
            #pragma unroll
            for (int mi = 0; mi < 2; mi++) {
                int r = wm*32 + mi*16 + grp;
                int c = ks*8 + tig;
                a[mi][0] = Ab[r * PA_ + c];
                a[mi][1] = Ab[(r + 8) * PA_ + c];
                a[mi][2] = Ab[r * PA_ + c + 4];
                a[mi][3] = Ab[(r + 8) * PA_ + c + 4];
            }
            float b[8][2];
            #pragma unroll
            for (int nf = 0; nf < 8; nf++) {
                int n = wn*64 + nf*8 + grp;
                if (BTRANS) {
                    b[nf][0] = Bb[n * PA_ + ks*8 + tig];
                    b[nf][1] = Bb[n * PA_ + ks*8 + tig + 4];
                } else {
                    b[nf][0] = Bb[(ks*8 + tig) * PB_ + n];
                    b[nf][1] = Bb[(ks*8 + tig + 4) * PB_ + n];
                }
            }
            #pragma unroll
            for (int mi = 0; mi < 2; mi++)
                #pragma unroll
                for (int nf = 0; nf < 8; nf++)
                    mma_tf32(acc[mi][nf], a[mi], b[nf]);
        }
        if (s < S - 1) {
            __syncthreads();
            float* Ac = Asm[(s + 1) & 1];
            float* Bc = Bsm[(s + 1) & 1];
            #pragma unroll
            for (int it = 0; it < 4; it++) {
                int idx = it * 1024 + tid * 4;
                *(float4*)&Ac[(idx >> 5) * PA_ + (idx & 31)] = to_tf32_4(pa[it]);
                if (BTRANS) *(float4*)&Bc[(idx >> 5) * PA_ + (idx & 31)] = to_tf32_4(pb[it]);
                else        *(float4*)&Bc[(idx >> 7) * PB_ + (idx & 127)] = to_tf32_4(pb[it]);
            }
            __syncthreads();
        }
    }

    // ---- epilogue
    #pragma unroll
    for (int mi = 0; mi < 2; mi++)
        #pragma unroll
        for (int hf = 0; hf < 2; hf++) {
            int row = m0 + wm*32 + mi*16 + grp + hf*8;
            #pragma unroll
            for (int nf = 0; nf < 8; nf++) {
                int col = n0 + wn*64 + nf*8 + tig*2;
                float v0 = acc[mi][nf][hf*2 + 0] + bias[col];
                float v1 = acc[mi][nf][hf*2 + 1] + bias[col + 1];
                if (EPI == 1) { v0 = fmaxf(v0, 0.f); v1 = fmaxf(v1, 0.f); }
                if (EPI == 2) {
                    v0 += add[(size_t)row * N + col];
                    v1 += add[(size_t)row * N + col + 1];
                }
                *(float2*)(C + (size_t)row * N + col) = make_float2(v0, v1);
            }
        }
}

// ---------------- fused relation GEMM (bf16 tensor core) + logits -------------
__global__ void __launch_bounds__(256, 1) relw_mma(
    const float* __restrict__ rel, const float* __restrict__ relw,
    const float* __restrict__ relb)
{
    extern __shared__ char smem[];
    const uint32_t AsBase = smem_u32(smem);
    const uint32_t BsBase = AsBase + 32768;
    float* red = (float*)smem;

    const int h   = blockIdx.x;
    const int n0  = blockIdx.y * 128;
    const int tid = threadIdx.x;
    const int lane = tid & 31, warp = tid >> 5;
    const int warp_m = warp >> 1, warp_n = warp & 1;

    float acc[2][8][4];
    #pragma unroll
    for (int i = 0; i < 2; i++)
        #pragma unroll
        for (int j = 0; j < 8; j++)
            #pragma unroll
            for (int k = 0; k < 4; k++) acc[i][j][k] = 0.f;

    const float* Arel = rel + (size_t)n0 * E_;
    const int kr = tid >> 2;
    const int dg = tid & 3;

    float4 ar[8], rar[4], rbr[4];

    {
        #pragma unroll
        for (int it = 0; it < 8; it++) {
            int idx = it * 1024 + tid * 4;
            ar[it] = *(const float4*)(Arel + (size_t)(idx >> 6) * E_ + (idx & 63));
        }
        const float* wra = relw + (size_t)kr * (2*E_) + h*64 + dg*16;
        #pragma unroll
        for (int i = 0; i < 4; i++) { rar[i] = ((const float4*)wra)[i]; rbr[i] = ((const float4*)(wra + E_))[i]; }
    }
    {
        char* Ab = smem;
        #pragma unroll
        for (int it = 0; it < 8; it++) {
            int idx = it * 1024 + tid * 4;
            int row = idx >> 6, col = idx & 63;
            uint2 v = make_uint2(f2bf2(ar[it].x, ar[it].y), f2bf2(ar[it].z, ar[it].w));
            *(uint2*)(Ab + row*128 + ((((col>>3) ^ (row&7)) << 4) | ((col&7) << 1))) = v;
        }
        char* Bb = smem + 32768;
        #pragma unroll
        for (int cj = 0; cj < 4; cj++) {
            const float* ra4 = (const float*)&rar[cj];
            const float* rb4 = (const float*)&rbr[cj];
            uint4 v = make_uint4(f2bf2(ra4[0], rb4[0]), f2bf2(ra4[1], rb4[1]),
                                 f2bf2(ra4[2], rb4[2]), f2bf2(ra4[3], rb4[3]));
            int chunk = (dg << 2) | cj;
            *(uint4*)(Bb + kr*256 + ((chunk ^ (kr&7)) << 4)) = v;
        }
    }
    __syncthreads();

    #pragma unroll
    for (int s = 0; s < 8; s++) {
        if (s < 7) {
            int k0 = (s + 1) * 64;
            #pragma unroll
            for (int it = 0; it < 8; it++) {
                int idx = it * 1024 + tid * 4;
                ar[it] = *(const float4*)(Arel + (size_t)(idx >> 6) * E_ + k0 + (idx & 63));
            }
            const float* wra = relw + (size_t)(k0 + kr) * (2*E_) + h*64 + dg*16;
            #pragma unroll
            for (int i = 0; i < 4; i++) { rar[i] = ((const float4*)wra)[i]; rbr[i] = ((const float4*)(wra + E_))[i]; }
        }
        const uint32_t Ab = AsBase + (s & 1) * 16384;
        const uint32_t Bb = BsBase + (s & 1) * 16384;
        #pragma unroll
        for (int ks = 0; ks < 4; ks++) {
            uint32_t a[2][4];
            #pragma unroll
            for (int mi = 0; mi < 2; mi++) {
                int r  = warp_m*32 + mi*16 + (lane & 15);
                int kc = ks*16 + ((lane >> 4) << 3);
                ldsm_x4(a[mi][0], a[mi][1], a[mi][2], a[mi][3],
                        Ab + r*128 + ((((kc >> 3) ^ (r & 7)) << 4)));
            }
            uint32_t b[8][2];
            #pragma unroll
            for (int g = 0; g < 4; g++) {
                int krow = ks*16 + (lane & 15);
                int ncol = warp_n*64 + g*16 + ((lane >> 4) << 3);
                ldsm_x4_t(b[2*g][0], b[2*g][1], b[2*g+1][0], b[2*g+1][1],
                          Bb + krow*256 + ((((ncol >> 3) ^ (krow & 7)) << 4)));
            }
            #pragma unroll
            for (int mi = 0; mi < 2; mi++)
                #pragma unroll
                for (int nf = 0; nf < 8; nf++)
                    mma16816(acc[mi][nf], a[mi], b[nf]);
        }
        if (s < 7) {
            __syncthreads();
            char* Abc = smem + ((s + 1) & 1) * 16384;
            #pragma unroll
            for (int it = 0; it < 8; it++) {
                int idx = it * 1024 + tid * 4;
                int row = idx >> 6, col = idx & 63;
                uint2 v = make_uint2(f2bf2(ar[it].x, ar[it].y), f2bf2(ar[it].z, ar[it].w));
                *(uint2*)(Abc + row*128 + ((((col>>3) ^ (row&7)) << 4) | ((col&7) << 1))) = v;
            }
            char* Bbc = smem + 32768 + ((s + 1) & 1) * 16384;
            #pragma unroll
            for (int cj = 0; cj < 4; cj++) {
                const float* ra4 = (const float*)&rar[cj];
                const float* rb4 = (const float*)&rbr[cj];
                uint4 v = make_uint4(f2bf2(ra4[0], rb4[0]), f2bf2(ra4[1], rb4[1]),
                                     f2bf2(ra4[2], rb4[2]), f2bf2(ra4[3], rb4[3]));
                int chunk = (dg << 2) | cj;
                *(uint4*)(Bbc + kr*256 + ((chunk ^ (kr&7)) << 4)) = v;
            }
            __syncthreads();
        }
    }

    const int tig = lane & 3, grp = lane >> 2;
    float part[2][2] = {{0.f, 0.f}, {0.f, 0.f}};
    #pragma unroll
    for (int nf = 0; nf < 8; nf++) {
        int d = warp_n*32 + nf*4 + tig;
        float bra = relb[h*64 + d];
        float brb = relb[E_ + h*64 + d];
        #pragma unroll
        for (int mi = 0; mi < 2; mi++)
            #pragma unroll
            for (int hf = 0; hf < 2; hf++) {
                int r  = warp_m*32 + mi*16 + grp + hf*8;
                int n  = n0 + r;
                int b  = n & 31;
                int ji = n >> 5;
                int ii = ji & 63, jj = ji >> 6;
                float q = g_qkv[(size_t)(ii*B_ + b) * (3*E_) + h*64 + d];
                float k = g_qkv[(size_t)(jj*B_ + b) * (3*E_) + E_ + h*64 + d];
                part[mi][hf] += (acc[mi][nf][hf*2+0] + bra + q) * (acc[mi][nf][hf*2+1] + brb + k);
            }
    }
    #pragma unroll
    for (int mi = 0; mi < 2; mi++)
        #pragma unroll
        for (int hf = 0; hf < 2; hf++) {
            float v = part[mi][hf];
            v += __shfl_xor_sync(~0u, v, 1);
            v += __shfl_xor_sync(~0u, v, 2);
            part[mi][hf] = v;
        }
    __syncthreads();
    if (tig == 0) {
        #pragma unroll
        for (int mi = 0; mi < 2; mi++)
            #pragma unroll
            for (int hf = 0; hf < 2; hf++) {
                int r = warp_m*32 + mi*16 + grp + hf*8;
                red[r*2 + warp_n] = part[mi][hf];
            }
    }
    __syncthreads();
    if (tid < 128) {
        int n  = n0 + tid;
        int b  = n & 31;
        int ji = n >> 5;
        int ii = ji & 63, jj = ji >> 6;
        g_w[((size_t)(ii*B_ + b) * H_ + h) * T_ + jj] =
            (red[tid*2] + red[tid*2 + 1]) * 0.015625f;
    }
}

// ---------------- softmax over j + attn = p @ v ------------------------------
__global__ __launch_bounds__(256) void softmax_attn_kernel()
{
    int ib = blockIdx.x;
    int b  = ib & 31;
    __shared__ float p[H_][T_];
    int t = threadIdx.x;
    int w = t >> 5, l = t & 31;

    float v0 = g_w[((size_t)ib*H_ + w)*T_ + l];
    float v1 = g_w[((size_t)ib*H_ + w)*T_ + l + 32];
    float mx = fmaxf(v0, v1);
    #pragma unroll
    for (int o = 16; o; o >>= 1) mx = fmaxf(mx, __shfl_xor_sync(~0u, mx, o));
    float e0 = expf(v0 - mx), e1 = expf(v1 - mx);
    float s = e0 + e1;
    #pragma unroll
    for (int o = 16; o; o >>= 1) s += __shfl_xor_sync(~0u, s, o);
    float inv = 1.0f / s;
    p[w][l]      = e0 * inv;
    p[w][l + 32] = e1 * inv;
    __syncthreads();

    #pragma unroll
    for (int c0 = 0; c0 < E_; c0 += 256) {
        int c = c0 + t;
        int hh = c >> 6, d = c & 63;
        float acc = 0.f;
        #pragma unroll 8
        for (int j = 0; j < T_; j++)
            acc += p[hh][j] * g_qkv[(size_t)(j*B_ + b) * (3*E_) + 2*E_ + hh*64 + d];
        g_attn[(size_t)ib * E_ + c] = acc;
    }
}

// ---------------- layernorm ----------------------------------------------------
__global__ __launch_bounds__(256) void ln_kernel(
    const float* __restrict__ in, const float* __restrict__ g,
    const float* __restrict__ b, float* __restrict__ out)
{
    int row = blockIdx.x;
    const float* r = in + (size_t)row * E_;
    int t = threadIdx.x;
    float v0 = r[t], v1 = r[t + 256];
    float s = v0 + v1, sq = v0*v0 + v1*v1;
    #pragma unroll
    for (int o = 16; o; o >>= 1) {
        s  += __shfl_xor_sync(~0u, s,  o);
        sq += __shfl_xor_sync(~0u, sq, o);
    }
    __shared__ float ss[8], ssq[8];
    int w = t >> 5, l = t & 31;
    if (l == 0) { ss[w] = s; ssq[w] = sq; }
    __syncthreads();
    if (w == 0) {
        s  = (l < 8) ? ss[l]  : 0.f;
        sq = (l < 8) ? ssq[l] : 0.f;
        #pragma unroll
        for (int o = 4; o; o >>= 1) {
            s  += __shfl_xor_sync(~0u, s,  o);
            sq += __shfl_xor_sync(~0u, sq, o);
        }
        if (l == 0) { ss[0] = s; ssq[0] = sq; }
    }
    __syncthreads();
    float mu   = ss[0]  * (1.f / E_);
    float var  = ssq[0] * (1.f / E_) - mu * mu;
    float rstd = rsqrtf(var + 1e-5f);
    out[(size_t)row*E_ + t]       = (v0 - mu) * rstd * g[t]       + b[t];
    out[(size_t)row*E_ + t + 256] = (v1 - mu) * rstd * g[t + 256] + b[t + 256];
}

// ---------------- launch --------------------------------------------------------
extern "C" void kernel_launch(void* const* d_in, const int* in_sizes, int n_in,
                              void* d_out, int out_size)
{
    const float* x        = (const float*)d_in[0];
    const float* relation = (const float*)d_in[1];
    const float* in_w     = (const float*)d_in[2];
    const float* in_b     = (const float*)d_in[3];
    const float* rel_w    = (const float*)d_in[4];
    const float* rel_b    = (const float*)d_in[5];
    const float* out_w    = (const float*)d_in[6];
    const float* out_b    = (const float*)d_in[7];
    const float* fc1_w    = (const float*)d_in[8];
    const float* fc1_b    = (const float*)d_in[9];
    const float* fc2_w    = (const float*)d_in[10];
    const float* fc2_b    = (const float*)d_in[11];
    const float* ln1_g    = (const float*)d_in[12];
    const float* ln1_b    = (const float*)d_in[13];
    const float* ln2_g    = (const float*)d_in[14];
    const float* ln2_b    = (const float*)d_in[15];
    float* out = (float*)d_out;

    const int SM_BT = (2*128*PA_ + 2*128*PA_) * 4;          // 73728
    const int SM_BN = (2*128*PA_ + 2*32*PB_) * 4;           // 71680

    static float *p_qkv = nullptr, *p_attn, *p_ao, *p_h, *p_f1, *p_f2;
    if (!p_qkv) {
        cudaGetSymbolAddress((void**)&p_qkv,  g_qkv);
        cudaGetSymbolAddress((void**)&p_attn, g_attn);
        cudaGetSymbolAddress((void**)&p_ao,   g_ao);
        cudaGetSymbolAddress((void**)&p_h,    g_h);
        cudaGetSymbolAddress((void**)&p_f1,   g_f1);
        cudaGetSymbolAddress((void**)&p_f2,   g_f2);
        cudaFuncSetAttribute(relw_mma, cudaFuncAttributeMaxDynamicSharedMemorySize, 65536);
        cudaFuncSetAttribute(gemm_tf32<true, 0>, cudaFuncAttributeMaxDynamicSharedMemorySize, SM_BT);
        cudaFuncSetAttribute(gemm_tf32<false, 1>, cudaFuncAttributeMaxDynamicSharedMemorySize, SM_BN);
        cudaFuncSetAttribute(gemm_tf32<false, 2>, cudaFuncAttributeMaxDynamicSharedMemorySize, SM_BN);
    }

    dim3 blk(256);

    // 1. qkv = x @ in_w^T + in_b    (tf32)
    gemm_tf32<true, 0><<<dim3(1536/128, TB_/128), blk, SM_BT>>>(x, in_w, in_b, nullptr, p_qkv, TB_, 3*E_, E_);

    // 2. fused relation GEMM (bf16 tensor core) + logits
    relw_mma<<<dim3(H_, ROWS_/128), blk, 65536>>>(relation, rel_w, rel_b);

    // 3. softmax + attn
    softmax_attn_kernel<<<TB_, 256>>>();

    // 4. out proj + residual       (tf32)
    gemm_tf32<false, 2><<<dim3(E_/128, TB_/128), blk, SM_BN>>>(p_attn, out_w, out_b, x, p_ao, TB_, E_, E_);

    // 5. LN1
    ln_kernel<<<TB_, 256>>>(p_ao, ln1_g, ln1_b, p_h);

    // 6. fc1 + relu                (tf32)
    gemm_tf32<false, 1><<<dim3(F_/128, TB_/128), blk, SM_BN>>>(p_h, fc1_w, fc1_b, nullptr, p_f1, TB_, F_, E_);

    // 7. fc2 + residual h          (tf32)
    gemm_tf32<false, 2><<<dim3(E_/128, TB_/128), blk, SM_BN>>>(p_f1, fc2_w, fc2_b, p_h, p_f2, TB_, E_, F_);

    // 8. LN2 -> out
    ln_kernel<<<TB_, 256>>>(p_f2, ln2_g, ln2_b, out);
}

// round 5
// speedup vs baseline: 5.1556x; 1.3514x over previous
#include <cuda_runtime.h>
#include <cuda_bf16.h>
#include <cstdint>

#define T_  64
#define B_  32
#define E_  512
#define H_  8
#define F_  2048
#define TB_ (T_*B_)        // 2048
#define ROWS_ (T_*T_*B_)   // 131072

// ---------------- scratch ----------------------------------------------------
__device__ float g_qkv[TB_ * 3 * E_];
__device__ float g_w[TB_ * H_ * T_];
__device__ float g_attn[TB_ * E_];
__device__ float g_ao[TB_ * E_];
__device__ float g_h[TB_ * E_];
__device__ float g_f1[TB_ * F_];
__device__ float g_f2[TB_ * E_];
__device__ __nv_bfloat16 g_arel[(size_t)ROWS_ * E_];   // relation in bf16 (134MB)
__device__ __nv_bfloat16 g_bw[H_ * E_ * 128];          // [h][k][2d interleaved ra/rb]

// ---------------- helpers ------------------------------------------------------
__device__ __forceinline__ uint32_t smem_u32(const void* p) {
    return (uint32_t)__cvta_generic_to_shared(p);
}
__device__ __forceinline__ void ldsm_x4(uint32_t& r0, uint32_t& r1, uint32_t& r2, uint32_t& r3, uint32_t a) {
    asm volatile("ldmatrix.sync.aligned.m8n8.x4.shared.b16 {%0,%1,%2,%3},[%4];"
                 : "=r"(r0), "=r"(r1), "=r"(r2), "=r"(r3) : "r"(a));
}
__device__ __forceinline__ void ldsm_x4_t(uint32_t& r0, uint32_t& r1, uint32_t& r2, uint32_t& r3, uint32_t a) {
    asm volatile("ldmatrix.sync.aligned.m8n8.x4.trans.shared.b16 {%0,%1,%2,%3},[%4];"
                 : "=r"(r0), "=r"(r1), "=r"(r2), "=r"(r3) : "r"(a));
}
__device__ __forceinline__ void mma16816(float* c, const uint32_t* a, const uint32_t* b) {
    asm volatile("mma.sync.aligned.m16n8k16.row.col.f32.bf16.bf16.f32 "
                 "{%0,%1,%2,%3},{%4,%5,%6,%7},{%8,%9},{%0,%1,%2,%3};"
                 : "+f"(c[0]), "+f"(c[1]), "+f"(c[2]), "+f"(c[3])
                 : "r"(a[0]), "r"(a[1]), "r"(a[2]), "r"(a[3]), "r"(b[0]), "r"(b[1]));
}
__device__ __forceinline__ void mma_tf32(float* c, const float* a, const float* b) {
    asm volatile("mma.sync.aligned.m16n8k8.row.col.f32.tf32.tf32.f32 "
                 "{%0,%1,%2,%3},{%4,%5,%6,%7},{%8,%9},{%0,%1,%2,%3};"
                 : "+f"(c[0]), "+f"(c[1]), "+f"(c[2]), "+f"(c[3])
                 : "r"(__float_as_uint(a[0])), "r"(__float_as_uint(a[1])),
                   "r"(__float_as_uint(a[2])), "r"(__float_as_uint(a[3])),
                   "r"(__float_as_uint(b[0])), "r"(__float_as_uint(b[1])));
}
__device__ __forceinline__ uint32_t f2bf2(float x, float y) {
    __nv_bfloat162 t = __floats2bfloat162_rn(x, y);
    return *reinterpret_cast<uint32_t*>(&t);
}
__device__ __forceinline__ float to_tf32(float x) {
    float y;
    asm("cvt.rna.tf32.f32 %0, %1;" : "=f"(y) : "f"(x));
    return y;
}
__device__ __forceinline__ float4 to_tf32_4(float4 v) {
    return make_float4(to_tf32(v.x), to_tf32(v.y), to_tf32(v.z), to_tf32(v.w));
}
#define CP_ASYNC16(saddr, gptr) \
    asm volatile("cp.async.cg.shared.global [%0], [%1], 16;" :: "r"(saddr), "l"(gptr) : "memory")
#define CP_COMMIT() asm volatile("cp.async.commit_group;" ::: "memory")
#define CP_WAIT1()  asm volatile("cp.async.wait_group 1;" ::: "memory")
#define CP_WAIT0()  asm volatile("cp.async.wait_group 0;" ::: "memory")

// ---------------- prepass: relation fp32 -> bf16 ------------------------------
__global__ __launch_bounds__(256) void cvt_rel(const float* __restrict__ rel)
{
    size_t i = ((size_t)blockIdx.x * 256 + threadIdx.x) * 8;
    float4 a = *(const float4*)(rel + i);
    float4 b = *(const float4*)(rel + i + 4);
    uint4 v = make_uint4(f2bf2(a.x, a.y), f2bf2(a.z, a.w),
                         f2bf2(b.x, b.y), f2bf2(b.z, b.w));
    *(uint4*)((char*)g_arel + i * 2) = v;
}

// ---------------- prepass: interleaved bf16 weight tiles [h][k][128] ----------
// col 2d = ra_d = relw[k][h*64+d], col 2d+1 = rb_d = relw[k][512+h*64+d]
__global__ __launch_bounds__(256) void build_bw(const float* __restrict__ relw)
{
    int idx = blockIdx.x * 256 + threadIdx.x;    // 8*512*64 = 262144
    int d = idx & 63;
    int k = (idx >> 6) & 511;
    int h = idx >> 15;
    g_bw[((size_t)h*E_ + k) * 128 + 2*d    ] = __float2bfloat16(relw[(size_t)k*(2*E_) + h*64 + d]);
    g_bw[((size_t)h*E_ + k) * 128 + 2*d + 1] = __float2bfloat16(relw[(size_t)k*(2*E_) + E_ + h*64 + d]);
}

// ---------------- fused relation GEMM (bf16 HMMA, cp.async) + logits ----------
// Block: 128 relation rows x one head. A: g_arel bf16, B: g_bw bf16. K=512, 8 stages.
__global__ void __launch_bounds__(256, 1) relw_mma(const float* __restrict__ relb)
{
    extern __shared__ char smem[];
    const uint32_t AsBase = smem_u32(smem);            // 2 x 16KB A bufs
    const uint32_t BsBase = AsBase + 32768;            // 2 x 16KB B bufs
    float* red = (float*)smem;

    const int h   = blockIdx.x;
    const int n0  = blockIdx.y * 128;
    const int tid = threadIdx.x;
    const int lane = tid & 31, warp = tid >> 5;
    const int warp_m = warp >> 1, warp_n = warp & 1;

    float acc[2][8][4];
    #pragma unroll
    for (int i = 0; i < 2; i++)
        #pragma unroll
        for (int j = 0; j < 8; j++)
            #pragma unroll
            for (int k = 0; k < 4; k++) acc[i][j][k] = 0.f;

    const __nv_bfloat16* Ag = g_arel + (size_t)n0 * E_;
    const __nv_bfloat16* Bg = g_bw + (size_t)h * E_ * 128;

    // ---- async stage loader: A 128x64 bf16 (row 128B, swizzled), B 64x128 bf16
    auto load_stage = [&](int s, int buf) {
        uint32_t Ab = AsBase + buf * 16384;
        #pragma unroll
        for (int c = 0; c < 4; c++) {
            int idx = c * 256 + tid;          // 1024 chunks of 16B
            int row = idx >> 3, cg = idx & 7;
            CP_ASYNC16(Ab + row*128 + (((cg ^ (row & 7)) << 4)),
                       Ag + (size_t)row * E_ + s*64 + cg*8);
        }
        uint32_t Bb = BsBase + buf * 16384;
        #pragma unroll
        for (int c = 0; c < 4; c++) {
            int idx = c * 256 + tid;
            int kr = idx >> 4, ng = idx & 15;
            CP_ASYNC16(Bb + kr*256 + (((ng ^ (kr & 7)) << 4)),
                       Bg + (size_t)(s*64 + kr) * 128 + ng*8);
        }
        CP_COMMIT();
    };

    load_stage(0, 0);

    #pragma unroll
    for (int s = 0; s < 8; s++) {
        if (s < 7) { load_stage(s + 1, (s + 1) & 1); CP_WAIT1(); }
        else       { CP_WAIT0(); }
        __syncthreads();

        const uint32_t Ab = AsBase + (s & 1) * 16384;
        const uint32_t Bb = BsBase + (s & 1) * 16384;
        #pragma unroll
        for (int ks = 0; ks < 4; ks++) {
            uint32_t a[2][4];
            #pragma unroll
            for (int mi = 0; mi < 2; mi++) {
                int r  = warp_m*32 + mi*16 + (lane & 15);
                int kc = ks*16 + ((lane >> 4) << 3);
                ldsm_x4(a[mi][0], a[mi][1], a[mi][2], a[mi][3],
                        Ab + r*128 + ((((kc >> 3) ^ (r & 7)) << 4)));
            }
            uint32_t b[8][2];
            #pragma unroll
            for (int g = 0; g < 4; g++) {
                int krow = ks*16 + (lane & 15);
                int ncol = warp_n*64 + g*16 + ((lane >> 4) << 3);
                ldsm_x4_t(b[2*g][0], b[2*g][1], b[2*g+1][0], b[2*g+1][1],
                          Bb + krow*256 + ((((ncol >> 3) ^ (krow & 7)) << 4)));
            }
            #pragma unroll
            for (int mi = 0; mi < 2; mi++)
                #pragma unroll
                for (int nf = 0; nf < 8; nf++)
                    mma16816(acc[mi][nf], a[mi], b[nf]);
        }
        __syncthreads();   // all warps done reading buf s before it's refilled at s+2
    }

    // ---- fused epilogue: (c0 + bra + q) * (c1 + brb + k), reduce over d --------
    const int tig = lane & 3, grp = lane >> 2;
    float part[2][2] = {{0.f, 0.f}, {0.f, 0.f}};
    #pragma unroll
    for (int nf = 0; nf < 8; nf++) {
        int d = warp_n*32 + nf*4 + tig;
        float bra = relb[h*64 + d];
        float brb = relb[E_ + h*64 + d];
        #pragma unroll
        for (int mi = 0; mi < 2; mi++)
            #pragma unroll
            for (int hf = 0; hf < 2; hf++) {
                int r  = warp_m*32 + mi*16 + grp + hf*8;
                int n  = n0 + r;
                int b  = n & 31;
                int ji = n >> 5;
                int ii = ji & 63, jj = ji >> 6;
                float q = g_qkv[(size_t)(ii*B_ + b) * (3*E_) + h*64 + d];
                float k = g_qkv[(size_t)(jj*B_ + b) * (3*E_) + E_ + h*64 + d];
                part[mi][hf] += (acc[mi][nf][hf*2+0] + bra + q) * (acc[mi][nf][hf*2+1] + brb + k);
            }
    }
    #pragma unroll
    for (int mi = 0; mi < 2; mi++)
        #pragma unroll
        for (int hf = 0; hf < 2; hf++) {
            float v = part[mi][hf];
            v += __shfl_xor_sync(~0u, v, 1);
            v += __shfl_xor_sync(~0u, v, 2);
            part[mi][hf] = v;
        }
    __syncthreads();
    if (tig == 0) {
        #pragma unroll
        for (int mi = 0; mi < 2; mi++)
            #pragma unroll
            for (int hf = 0; hf < 2; hf++) {
                int r = warp_m*32 + mi*16 + grp + hf*8;
                red[r*2 + warp_n] = part[mi][hf];
            }
    }
    __syncthreads();
    if (tid < 128) {
        int n  = n0 + tid;
        int b  = n & 31;
        int ji = n >> 5;
        int ii = ji & 63, jj = ji >> 6;
        g_w[((size_t)(ii*B_ + b) * H_ + h) * T_ + jj] =
            (red[tid*2] + red[tid*2 + 1]) * 0.015625f;
    }
}

// ---------------- tf32 GEMM: 128x128 tile, K-stage 32, padded-scalar smem -----
#define PA_ 36
#define PB_ 136
template<bool BTRANS, int EPI>
__global__ __launch_bounds__(256) void gemm_tf32(
    const float* __restrict__ A, const float* __restrict__ Bm,
    const float* __restrict__ bias, const float* __restrict__ add,
    float* __restrict__ C, int M, int N, int K)
{
    extern __shared__ float sm[];
    const int AW = 128 * PA_;
    const int BW = BTRANS ? 128 * PA_ : 32 * PB_;
    float* Asm[2] = { sm, sm + AW };
    float* Bsm[2] = { sm + 2*AW, sm + 2*AW + BW };

    const int tid = threadIdx.x;
    const int lane = tid & 31, warp = tid >> 5;
    const int wm = warp >> 1, wn = warp & 1;
    const int grp = lane >> 2, tig = lane & 3;
    const int m0 = blockIdx.y * 128;
    const int n0 = blockIdx.x * 128;

    float acc[2][8][4];
    #pragma unroll
    for (int i = 0; i < 2; i++)
        #pragma unroll
        for (int j = 0; j < 8; j++)
            #pragma unroll
            for (int k = 0; k < 4; k++) acc[i][j][k] = 0.f;

    const int S = K >> 5;
    float4 pa[4], pb[4];

    #pragma unroll
    for (int it = 0; it < 4; it++) {
        int idx = it * 1024 + tid * 4;
        pa[it] = *(const float4*)(A + (size_t)(m0 + (idx >> 5)) * K + (idx & 31));
        if (BTRANS) pb[it] = *(const float4*)(Bm + (size_t)(n0 + (idx >> 5)) * K + (idx & 31));
        else        pb[it] = *(const float4*)(Bm + (size_t)(idx >> 7) * N + n0 + (idx & 127));
    }
    #pragma unroll
    for (int it = 0; it < 4; it++) {
        int idx = it * 1024 + tid * 4;
        *(float4*)&Asm[0][(idx >> 5) * PA_ + (idx & 31)] = to_tf32_4(pa[it]);
        if (BTRANS) *(float4*)&Bsm[0][(idx >> 5) * PA_ + (idx & 31)] = to_tf32_4(pb[it]);
        else        *(float4*)&Bsm[0][(idx >> 7) * PB_ + (idx & 127)] = to_tf32_4(pb[it]);
    }
    __syncthreads();

    for (int s = 0; s < S; s++) {
        if (s < S - 1) {
            int k0 = (s + 1) * 32;
            #pragma unroll
            for (int it = 0; it < 4; it++) {
                int idx = it * 1024 + tid * 4;
                pa[it] = *(const float4*)(A + (size_t)(m0 + (idx >> 5)) * K + k0 + (idx & 31));
                if (BTRANS) pb[it] = *(const float4*)(Bm + (size_t)(n0 + (idx >> 5)) * K + k0 + (idx & 31));
                else        pb[it] = *(const float4*)(Bm + (size_t)(k0 + (idx >> 7)) * N + n0 + (idx & 127));
            }
        }
        const float* Ab = Asm[s & 1];
        const float* Bb = Bsm[s & 1];
        #pragma unroll
        for (int ks = 0; ks < 4; ks++) {
            float a[2][4];
            #pragma unroll
            for (int mi = 0; mi < 2; mi++) {
                int r = wm*32 + mi*16 + grp;
                int c = ks*8 + tig;
                a[mi][0] = Ab[r * PA_ + c];
                a[mi][1] = Ab[(r + 8) * PA_ + c];
                a[mi][2] = Ab[r * PA_ + c + 4];
                a[mi][3] = Ab[(r + 8) * PA_ + c + 4];
            }
            float b[8][2];
            #pragma unroll
            for (int nf = 0; nf < 8; nf++) {
                int n = wn*64 + nf*8 + grp;
                if (BTRANS) {
                    b[nf][0] = Bb[n * PA_ + ks*8 + tig];
                    b[nf][1] = Bb[n * PA_ + ks*8 + tig + 4];
                } else {
                    b[nf][0] = Bb[(ks*8 + tig) * PB_ + n];
                    b[nf][1] = Bb[(ks*8 + tig + 4) * PB_ + n];
                }
            }
            #pragma unroll
            for (int mi = 0; mi < 2; mi++)
                #pragma unroll
                for (int nf = 0; nf < 8; nf++)
                    mma_tf32(acc[mi][nf], a[mi], b[nf]);
        }
        if (s < S - 1) {
            __syncthreads();
            float* Ac = Asm[(s + 1) & 1];
            float* Bc = Bsm[(s + 1) & 1];
            #pragma unroll
            for (int it = 0; it < 4; it++) {
                int idx = it * 1024 + tid * 4;
                *(float4*)&Ac[(idx >> 5) * PA_ + (idx & 31)] = to_tf32_4(pa[it]);
                if (BTRANS) *(float4*)&Bc[(idx >> 5) * PA_ + (idx & 31)] = to_tf32_4(pb[it]);
                else        *(float4*)&Bc[(idx >> 7) * PB_ + (idx & 127)] = to_tf32_4(pb[it]);
            }
            __syncthreads();
        }
    }

    #pragma unroll
    for (int mi = 0; mi < 2; mi++)
        #pragma unroll
        for (int hf = 0; hf < 2; hf++) {
            int row = m0 + wm*32 + mi*16 + grp + hf*8;
            #pragma unroll
            for (int nf = 0; nf < 8; nf++) {
                int col = n0 + wn*64 + nf*8 + tig*2;
                float v0 = acc[mi][nf][hf*2 + 0] + bias[col];
                float v1 = acc[mi][nf][hf*2 + 1] + bias[col + 1];
                if (EPI == 1) { v0 = fmaxf(v0, 0.f); v1 = fmaxf(v1, 0.f); }
                if (EPI == 2) {
                    v0 += add[(size_t)row * N + col];
                    v1 += add[(size_t)row * N + col + 1];
                }
                *(float2*)(C + (size_t)row * N + col) = make_float2(v0, v1);
            }
        }
}

// ---------------- softmax over j + attn = p @ v ------------------------------
__global__ __launch_bounds__(256) void softmax_attn_kernel()
{
    int ib = blockIdx.x;
    int b  = ib & 31;
    __shared__ float p[H_][T_];
    int t = threadIdx.x;
    int w = t >> 5, l = t & 31;

    float v0 = g_w[((size_t)ib*H_ + w)*T_ + l];
    float v1 = g_w[((size_t)ib*H_ + w)*T_ + l + 32];
    float mx = fmaxf(v0, v1);
    #pragma unroll
    for (int o = 16; o; o >>= 1) mx = fmaxf(mx, __shfl_xor_sync(~0u, mx, o));
    float e0 = expf(v0 - mx), e1 = expf(v1 - mx);
    float s = e0 + e1;
    #pragma unroll
    for (int o = 16; o; o >>= 1) s += __shfl_xor_sync(~0u, s, o);
    float inv = 1.0f / s;
    p[w][l]      = e0 * inv;
    p[w][l + 32] = e1 * inv;
    __syncthreads();

    #pragma unroll
    for (int c0 = 0; c0 < E_; c0 += 256) {
        int c = c0 + t;
        int hh = c >> 6, d = c & 63;
        float acc = 0.f;
        #pragma unroll 8
        for (int j = 0; j < T_; j++)
            acc += p[hh][j] * g_qkv[(size_t)(j*B_ + b) * (3*E_) + 2*E_ + hh*64 + d];
        g_attn[(size_t)ib * E_ + c] = acc;
    }
}

// ---------------- layernorm ----------------------------------------------------
__global__ __launch_bounds__(256) void ln_kernel(
    const float* __restrict__ in, const float* __restrict__ g,
    const float* __restrict__ b, float* __restrict__ out)
{
    int row = blockIdx.x;
    const float* r = in + (size_t)row * E_;
    int t = threadIdx.x;
    float v0 = r[t], v1 = r[t + 256];
    float s = v0 + v1, sq = v0*v0 + v1*v1;
    #pragma unroll
    for (int o = 16; o; o >>= 1) {
        s  += __shfl_xor_sync(~0u, s,  o);
        sq += __shfl_xor_sync(~0u, sq, o);
    }
    __shared__ float ss[8], ssq[8];
    int w = t >> 5, l = t & 31;
    if (l == 0) { ss[w] = s; ssq[w] = sq; }
    __syncthreads();
    if (w == 0) {
        s  = (l < 8) ? ss[l]  : 0.f;
        sq = (l < 8) ? ssq[l] : 0.f;
        #pragma unroll
        for (int o = 4; o; o >>= 1) {
            s  += __shfl_xor_sync(~0u, s,  o);
            sq += __shfl_xor_sync(~0u, sq, o);
        }
        if (l == 0) { ss[0] = s; ssq[0] = sq; }
    }
    __syncthreads();
    float mu   = ss[0]  * (1.f / E_);
    float var  = ssq[0] * (1.f / E_) - mu * mu;
    float rstd = rsqrtf(var + 1e-5f);
    out[(size_t)row*E_ + t]       = (v0 - mu) * rstd * g[t]       + b[t];
    out[(size_t)row*E_ + t + 256] = (v1 - mu) * rstd * g[t + 256] + b[t + 256];
}

// ---------------- launch --------------------------------------------------------
extern "C" void kernel_launch(void* const* d_in, const int* in_sizes, int n_in,
                              void* d_out, int out_size)
{
    const float* x        = (const float*)d_in[0];
    const float* relation = (const float*)d_in[1];
    const float* in_w     = (const float*)d_in[2];
    const float* in_b     = (const float*)d_in[3];
    const float* rel_w    = (const float*)d_in[4];
    const float* rel_b    = (const float*)d_in[5];
    const float* out_w    = (const float*)d_in[6];
    const float* out_b    = (const float*)d_in[7];
    const float* fc1_w    = (const float*)d_in[8];
    const float* fc1_b    = (const float*)d_in[9];
    const float* fc2_w    = (const float*)d_in[10];
    const float* fc2_b    = (const float*)d_in[11];
    const float* ln1_g    = (const float*)d_in[12];
    const float* ln1_b    = (const float*)d_in[13];
    const float* ln2_g    = (const float*)d_in[14];
    const float* ln2_b    = (const float*)d_in[15];
    float* out = (float*)d_out;

    const int SM_BT = (2*128*PA_ + 2*128*PA_) * 4;
    const int SM_BN = (2*128*PA_ + 2*32*PB_) * 4;

    static float *p_qkv = nullptr, *p_attn, *p_ao, *p_h, *p_f1, *p_f2;
    if (!p_qkv) {
        cudaGetSymbolAddress((void**)&p_qkv,  g_qkv);
        cudaGetSymbolAddress((void**)&p_attn, g_attn);
        cudaGetSymbolAddress((void**)&p_ao,   g_ao);
        cudaGetSymbolAddress((void**)&p_h,    g_h);
        cudaGetSymbolAddress((void**)&p_f1,   g_f1);
        cudaGetSymbolAddress((void**)&p_f2,   g_f2);
        cudaFuncSetAttribute(relw_mma, cudaFuncAttributeMaxDynamicSharedMemorySize, 65536);
        cudaFuncSetAttribute(gemm_tf32<true, 0>, cudaFuncAttributeMaxDynamicSharedMemorySize, SM_BT);
        cudaFuncSetAttribute(gemm_tf32<false, 1>, cudaFuncAttributeMaxDynamicSharedMemorySize, SM_BN);
        cudaFuncSetAttribute(gemm_tf32<false, 2>, cudaFuncAttributeMaxDynamicSharedMemorySize, SM_BN);
    }

    dim3 blk(256);

    // 0a. prepass: relation -> bf16 (134MB)
    cvt_rel<<<ROWS_ * E_ / (8 * 256), 256>>>(relation);
    // 0b. prepass: interleaved bf16 weight tiles [h][k][128]
    build_bw<<<1024, 256>>>(rel_w);

    // 1. qkv = x @ in_w^T + in_b    (tf32)
    gemm_tf32<true, 0><<<dim3(1536/128, TB_/128), blk, SM_BT>>>(x, in_w, in_b, nullptr, p_qkv, TB_, 3*E_, E_);

    // 2. relation GEMM (bf16 HMMA + cp.async) + fused logits
    relw_mma<<<dim3(H_, ROWS_/128), blk, 65536>>>(rel_b);

    // 3. softmax + attn
    softmax_attn_kernel<<<TB_, 256>>>();

    // 4. out proj + residual       (tf32)
    gemm_tf32<false, 2><<<dim3(E_/128, TB_/128), blk, SM_BN>>>(p_attn, out_w, out_b, x, p_ao, TB_, E_, E_);

    // 5. LN1
    ln_kernel<<<TB_, 256>>>(p_ao, ln1_g, ln1_b, p_h);

    // 6. fc1 + relu                (tf32)
    gemm_tf32<false, 1><<<dim3(F_/128, TB_/128), blk, SM_BN>>>(p_h, fc1_w, fc1_b, nullptr, p_f1, TB_, F_, E_);

    // 7. fc2 + residual h          (tf32)
    gemm_tf32<false, 2><<<dim3(E_/128, TB_/128), blk, SM_BN>>>(p_f1, fc2_w, fc2_b, p_h, p_f2, TB_, E_, F_);

    // 8. LN2 -> out
    ln_kernel<<<TB_, 256>>>(p_f2, ln2_g, ln2_b, out);
}

// round 6
// speedup vs baseline: 5.1641x; 1.0016x over previous
#include <cuda_runtime.h>
#include <cuda_bf16.h>
#include <cstdint>

#define T_  64
#define B_  32
#define E_  512
#define H_  8
#define F_  2048
#define TB_ (T_*B_)        // 2048
#define ROWS_ (T_*T_*B_)   // 131072

// ---------------- scratch ----------------------------------------------------
__device__ float g_qkv[TB_ * 3 * E_];
__device__ float g_w[TB_ * H_ * T_];
__device__ float g_attn[TB_ * E_];
__device__ float g_ao[TB_ * E_];
__device__ float g_h[TB_ * E_];
__device__ float g_f1[TB_ * F_];
__device__ float g_f2[TB_ * E_];
__device__ __nv_bfloat16 g_arel[(size_t)ROWS_ * E_];   // relation in bf16 (134MB)
__device__ __nv_bfloat16 g_bw[H_ * E_ * 128];          // [h][k][2d interleaved ra/rb]

// ---------------- helpers ------------------------------------------------------
__device__ __forceinline__ uint32_t smem_u32(const void* p) {
    return (uint32_t)__cvta_generic_to_shared(p);
}
__device__ __forceinline__ void ldsm_x4(uint32_t& r0, uint32_t& r1, uint32_t& r2, uint32_t& r3, uint32_t a) {
    asm volatile("ldmatrix.sync.aligned.m8n8.x4.shared.b16 {%0,%1,%2,%3},[%4];"
                 : "=r"(r0), "=r"(r1), "=r"(r2), "=r"(r3) : "r"(a));
}
__device__ __forceinline__ void ldsm_x4_t(uint32_t& r0, uint32_t& r1, uint32_t& r2, uint32_t& r3, uint32_t a) {
    asm volatile("ldmatrix.sync.aligned.m8n8.x4.trans.shared.b16 {%0,%1,%2,%3},[%4];"
                 : "=r"(r0), "=r"(r1), "=r"(r2), "=r"(r3) : "r"(a));
}
__device__ __forceinline__ void mma16816(float* c, const uint32_t* a, const uint32_t* b) {
    asm volatile("mma.sync.aligned.m16n8k16.row.col.f32.bf16.bf16.f32 "
                 "{%0,%1,%2,%3},{%4,%5,%6,%7},{%8,%9},{%0,%1,%2,%3};"
                 : "+f"(c[0]), "+f"(c[1]), "+f"(c[2]), "+f"(c[3])
                 : "r"(a[0]), "r"(a[1]), "r"(a[2]), "r"(a[3]), "r"(b[0]), "r"(b[1]));
}
__device__ __forceinline__ void mma_tf32(float* c, const float* a, const float* b) {
    asm volatile("mma.sync.aligned.m16n8k8.row.col.f32.tf32.tf32.f32 "
                 "{%0,%1,%2,%3},{%4,%5,%6,%7},{%8,%9},{%0,%1,%2,%3};"
                 : "+f"(c[0]), "+f"(c[1]), "+f"(c[2]), "+f"(c[3])
                 : "r"(__float_as_uint(a[0])), "r"(__float_as_uint(a[1])),
                   "r"(__float_as_uint(a[2])), "r"(__float_as_uint(a[3])),
                   "r"(__float_as_uint(b[0])), "r"(__float_as_uint(b[1])));
}
__device__ __forceinline__ uint32_t f2bf2(float x, float y) {
    __nv_bfloat162 t = __floats2bfloat162_rn(x, y);
    return *reinterpret_cast<uint32_t*>(&t);
}
__device__ __forceinline__ float to_tf32(float x) {
    float y;
    asm("cvt.rna.tf32.f32 %0, %1;" : "=f"(y) : "f"(x));
    return y;
}
__device__ __forceinline__ float4 to_tf32_4(float4 v) {
    return make_float4(to_tf32(v.x), to_tf32(v.y), to_tf32(v.z), to_tf32(v.w));
}
#define CP_ASYNC16(saddr, gptr) \
    asm volatile("cp.async.cg.shared.global [%0], [%1], 16;" :: "r"(saddr), "l"(gptr) : "memory")
#define CP_COMMIT() asm volatile("cp.async.commit_group;" ::: "memory")
#define CP_WAIT1()  asm volatile("cp.async.wait_group 1;" ::: "memory")
#define CP_WAIT0()  asm volatile("cp.async.wait_group 0;" ::: "memory")

// ---------------- prepass: relation fp32 -> bf16 ------------------------------
__global__ __launch_bounds__(256) void cvt_rel(const float* __restrict__ rel)
{
    size_t i = ((size_t)blockIdx.x * 256 + threadIdx.x) * 8;
    float4 a = *(const float4*)(rel + i);
    float4 b = *(const float4*)(rel + i + 4);
    uint4 v = make_uint4(f2bf2(a.x, a.y), f2bf2(a.z, a.w),
                         f2bf2(b.x, b.y), f2bf2(b.z, b.w));
    *(uint4*)((char*)g_arel + i * 2) = v;
}

// ---------------- prepass: interleaved bf16 weight tiles [h][k][128] ----------
__global__ __launch_bounds__(256) void build_bw(const float* __restrict__ relw)
{
    int idx = blockIdx.x * 256 + threadIdx.x;    // 262144
    int d = idx & 63;
    int k = (idx >> 6) & 511;
    int h = idx >> 15;
    g_bw[((size_t)h*E_ + k) * 128 + 2*d    ] = __float2bfloat16(relw[(size_t)k*(2*E_) + h*64 + d]);
    g_bw[((size_t)h*E_ + k) * 128 + 2*d + 1] = __float2bfloat16(relw[(size_t)k*(2*E_) + E_ + h*64 + d]);
}

// ---------------- fused relation GEMM (bf16 HMMA, 3-stage cp.async) -----------
// Block: 128 relation rows x one head. K=512, 8 K-stages of 64, 3 smem buffers,
// ONE barrier per stage, ldsm frags double-buffered across k-slices.
__global__ void __launch_bounds__(256, 1) relw_mma(const float* __restrict__ relb)
{
    extern __shared__ char smem[];
    const uint32_t AsBase = smem_u32(smem);            // 3 x 16KB A bufs
    const uint32_t BsBase = AsBase + 49152;            // 3 x 16KB B bufs
    float* red = (float*)smem;

    const int h   = blockIdx.x;
    const int n0  = blockIdx.y * 128;
    const int tid = threadIdx.x;
    const int lane = tid & 31, warp = tid >> 5;
    const int warp_m = warp >> 1, warp_n = warp & 1;

    float acc[2][8][4];
    #pragma unroll
    for (int i = 0; i < 2; i++)
        #pragma unroll
        for (int j = 0; j < 8; j++)
            #pragma unroll
            for (int k = 0; k < 4; k++) acc[i][j][k] = 0.f;

    const __nv_bfloat16* Ag = g_arel + (size_t)n0 * E_;
    const __nv_bfloat16* Bg = g_bw + (size_t)h * E_ * 128;

    auto load_stage = [&](int s, int buf) {
        uint32_t Ab = AsBase + buf * 16384;
        #pragma unroll
        for (int c = 0; c < 4; c++) {
            int idx = c * 256 + tid;          // 1024 chunks of 16B
            int row = idx >> 3, cg = idx & 7;
            CP_ASYNC16(Ab + row*128 + (((cg ^ (row & 7)) << 4)),
                       Ag + (size_t)row * E_ + s*64 + cg*8);
        }
        uint32_t Bb = BsBase + buf * 16384;
        #pragma unroll
        for (int c = 0; c < 4; c++) {
            int idx = c * 256 + tid;
            int kr = idx >> 4, ng = idx & 15;
            CP_ASYNC16(Bb + kr*256 + (((ng ^ (kr & 7)) << 4)),
                       Bg + (size_t)(s*64 + kr) * 128 + ng*8);
        }
        CP_COMMIT();
    };

    // lane-invariant fragment address components
    const int a_r  = warp_m*32 + (lane & 15);          // +mi*16
    const int a_kc = (lane >> 4) << 3;                 // +ks*16
    const int b_kr = lane & 15;                        // +ks*16
    const int b_nc = warp_n*64 + ((lane >> 4) << 3);   // +g*16

    auto load_frags = [&](uint32_t Ab, uint32_t Bb, int ks,
                          uint32_t a[2][4], uint32_t b[8][2]) {
        #pragma unroll
        for (int mi = 0; mi < 2; mi++) {
            int r  = a_r + mi*16;
            int kc = a_kc + ks*16;
            ldsm_x4(a[mi][0], a[mi][1], a[mi][2], a[mi][3],
                    Ab + r*128 + ((((kc >> 3) ^ (r & 7)) << 4)));
        }
        #pragma unroll
        for (int g = 0; g < 4; g++) {
            int krow = b_kr + ks*16;
            int ncol = b_nc + g*16;
            ldsm_x4_t(b[2*g][0], b[2*g][1], b[2*g+1][0], b[2*g+1][1],
                      Bb + krow*256 + ((((ncol >> 3) ^ (krow & 7)) << 4)));
        }
    };

    load_stage(0, 0);
    load_stage(1, 1);

    uint32_t afr[2][2][4], bfr[2][8][2];

    #pragma unroll
    for (int s = 0; s < 8; s++) {
        if (s < 6)      { load_stage(s + 2, (s + 2) % 3); CP_WAIT1(); }
        else if (s == 6){ CP_WAIT1(); }
        else            { CP_WAIT0(); }
        __syncthreads();

        const uint32_t Ab = AsBase + (s % 3) * 16384;
        const uint32_t Bb = BsBase + (s % 3) * 16384;

        load_frags(Ab, Bb, 0, afr[0], bfr[0]);
        #pragma unroll
        for (int ks = 0; ks < 4; ks++) {
            if (ks < 3) load_frags(Ab, Bb, ks + 1, afr[(ks + 1) & 1], bfr[(ks + 1) & 1]);
            #pragma unroll
            for (int mi = 0; mi < 2; mi++)
                #pragma unroll
                for (int nf = 0; nf < 8; nf++)
                    mma16816(acc[mi][nf], afr[ks & 1][mi], bfr[ks & 1][nf]);
        }
        // no trailing barrier: 3 buffers + leading barrier bound warp drift
    }

    // ---- fused epilogue: (c0 + bra + q) * (c1 + brb + k), reduce over d --------
    const int tig = lane & 3, grp = lane >> 2;
    float part[2][2] = {{0.f, 0.f}, {0.f, 0.f}};
    #pragma unroll
    for (int nf = 0; nf < 8; nf++) {
        int d = warp_n*32 + nf*4 + tig;
        float bra = relb[h*64 + d];
        float brb = relb[E_ + h*64 + d];
        #pragma unroll
        for (int mi = 0; mi < 2; mi++)
            #pragma unroll
            for (int hf = 0; hf < 2; hf++) {
                int r  = warp_m*32 + mi*16 + grp + hf*8;
                int n  = n0 + r;
                int b  = n & 31;
                int ji = n >> 5;
                int ii = ji & 63, jj = ji >> 6;
                float q = g_qkv[(size_t)(ii*B_ + b) * (3*E_) + h*64 + d];
                float k = g_qkv[(size_t)(jj*B_ + b) * (3*E_) + E_ + h*64 + d];
                part[mi][hf] += (acc[mi][nf][hf*2+0] + bra + q) * (acc[mi][nf][hf*2+1] + brb + k);
            }
    }
    #pragma unroll
    for (int mi = 0; mi < 2; mi++)
        #pragma unroll
        for (int hf = 0; hf < 2; hf++) {
            float v = part[mi][hf];
            v += __shfl_xor_sync(~0u, v, 1);
            v += __shfl_xor_sync(~0u, v, 2);
            part[mi][hf] = v;
        }
    __syncthreads();
    if (tig == 0) {
        #pragma unroll
        for (int mi = 0; mi < 2; mi++)
            #pragma unroll
            for (int hf = 0; hf < 2; hf++) {
                int r = warp_m*32 + mi*16 + grp + hf*8;
                red[r*2 + warp_n] = part[mi][hf];
            }
    }
    __syncthreads();
    if (tid < 128) {
        int n  = n0 + tid;
        int b  = n & 31;
        int ji = n >> 5;
        int ii = ji & 63, jj = ji >> 6;
        g_w[((size_t)(ii*B_ + b) * H_ + h) * T_ + jj] =
            (red[tid*2] + red[tid*2 + 1]) * 0.015625f;
    }
}

// ---------------- tf32 GEMM: 128x128 tile, K-stage 32, padded-scalar smem -----
#define PA_ 36
#define PB_ 136
template<bool BTRANS, int EPI>
__global__ __launch_bounds__(256) void gemm_tf32(
    const float* __restrict__ A, const float* __restrict__ Bm,
    const float* __restrict__ bias, const float* __restrict__ add,
    float* __restrict__ C, int M, int N, int K)
{
    extern __shared__ float sm[];
    const int AW = 128 * PA_;
    const int BW = BTRANS ? 128 * PA_ : 32 * PB_;
    float* Asm[2] = { sm, sm + AW };
    float* Bsm[2] = { sm + 2*AW, sm + 2*AW + BW };

    const int tid = threadIdx.x;
    const int lane = tid & 31, warp = tid >> 5;
    const int wm = warp >> 1, wn = warp & 1;
    const int grp = lane >> 2, tig = lane & 3;
    const int m0 = blockIdx.y * 128;
    const int n0 = blockIdx.x * 128;

    float acc[2][8][4];
    #pragma unroll
    for (int i = 0; i < 2; i++)
        #pragma unroll
        for (int j = 0; j < 8; j++)
            #pragma unroll
            for (int k = 0; k < 4; k++) acc[i][j][k] = 0.f;

    const int S = K >> 5;
    float4 pa[4], pb[4];

    #pragma unroll
    for (int it = 0; it < 4; it++) {
        int idx = it * 1024 + tid * 4;
        pa[it] = *(const float4*)(A + (size_t)(m0 + (idx >> 5)) * K + (idx & 31));
        if (BTRANS) pb[it] = *(const float4*)(Bm + (size_t)(n0 + (idx >> 5)) * K + (idx & 31));
        else        pb[it] = *(const float4*)(Bm + (size_t)(idx >> 7) * N + n0 + (idx & 127));
    }
    #pragma unroll
    for (int it = 0; it < 4; it++) {
        int idx = it * 1024 + tid * 4;
        *(float4*)&Asm[0][(idx >> 5) * PA_ + (idx & 31)] = to_tf32_4(pa[it]);
        if (BTRANS) *(float4*)&Bsm[0][(idx >> 5) * PA_ + (idx & 31)] = to_tf32_4(pb[it]);
        else        *(float4*)&Bsm[0][(idx >> 7) * PB_ + (idx & 127)] = to_tf32_4(pb[it]);
    }
    __syncthreads();

    for (int s = 0; s < S; s++) {
        if (s < S - 1) {
            int k0 = (s + 1) * 32;
            #pragma unroll
            for (int it = 0; it < 4; it++) {
                int idx = it * 1024 + tid * 4;
                pa[it] = *(const float4*)(A + (size_t)(m0 + (idx >> 5)) * K + k0 + (idx & 31));
                if (BTRANS) pb[it] = *(const float4*)(Bm + (size_t)(n0 + (idx >> 5)) * K + k0 + (idx & 31));
                else        pb[it] = *(const float4*)(Bm + (size_t)(k0 + (idx >> 7)) * N + n0 + (idx & 127));
            }
        }
        const float* Ab = Asm[s & 1];
        const float* Bb = Bsm[s & 1];
        #pragma unroll
        for (int ks = 0; ks < 4; ks++) {
            float a[2][4];
            #pragma unroll
            for (int mi = 0; mi < 2; mi++) {
                int r = wm*32 + mi*16 + grp;
                int c = ks*8 + tig;
                a[mi][0] = Ab[r * PA_ + c];
                a[mi][1] = Ab[(r + 8) * PA_ + c];
                a[mi][2] = Ab[r * PA_ + c + 4];
                a[mi][3] = Ab[(r + 8) * PA_ + c + 4];
            }
            float b[8][2];
            #pragma unroll
            for (int nf = 0; nf < 8; nf++) {
                int n = wn*64 + nf*8 + grp;
                if (BTRANS) {
                    b[nf][0] = Bb[n * PA_ + ks*8 + tig];
                    b[nf][1] = Bb[n * PA_ + ks*8 + tig + 4];
                } else {
                    b[nf][0] = Bb[(ks*8 + tig) * PB_ + n];
                    b[nf][1] = Bb[(ks*8 + tig + 4) * PB_ + n];
                }
            }
            #pragma unroll
            for (int mi = 0; mi < 2; mi++)
                #pragma unroll
                for (int nf = 0; nf < 8; nf++)
                    mma_tf32(acc[mi][nf], a[mi], b[nf]);
        }
        if (s < S - 1) {
            __syncthreads();
            float* Ac = Asm[(s + 1) & 1];
            float* Bc = Bsm[(s + 1) & 1];
            #pragma unroll
            for (int it = 0; it < 4; it++) {
                int idx = it * 1024 + tid * 4;
                *(float4*)&Ac[(idx >> 5) * PA_ + (idx & 31)] = to_tf32_4(pa[it]);
                if (BTRANS) *(float4*)&Bc[(idx >> 5) * PA_ + (idx & 31)] = to_tf32_4(pb[it]);
                else        *(float4*)&Bc[(idx >> 7) * PB_ + (idx & 127)] = to_tf32_4(pb[it]);
            }
            __syncthreads();
        }
    }

    #pragma unroll
    for (int mi = 0; mi < 2; mi++)
        #pragma unroll
        for (int hf = 0; hf < 2; hf++) {
            int row = m0 + wm*32 + mi*16 + grp + hf*8;
            #pragma unroll
            for (int nf = 0; nf < 8; nf++) {
                int col = n0 + wn*64 + nf*8 + tig*2;
                float v0 = acc[mi][nf][hf*2 + 0] + bias[col];
                float v1 = acc[mi][nf][hf*2 + 1] + bias[col + 1];
                if (EPI == 1) { v0 = fmaxf(v0, 0.f); v1 = fmaxf(v1, 0.f); }
                if (EPI == 2) {
                    v0 += add[(size_t)row * N + col];
                    v1 += add[(size_t)row * N + col + 1];
                }
                *(float2*)(C + (size_t)row * N + col) = make_float2(v0, v1);
            }
        }
}

// ---------------- softmax over j + attn = p @ v ------------------------------
__global__ __launch_bounds__(256) void softmax_attn_kernel()
{
    int ib = blockIdx.x;
    int b  = ib & 31;
    __shared__ float p[H_][T_];
    int t = threadIdx.x;
    int w = t >> 5, l = t & 31;

    float v0 = g_w[((size_t)ib*H_ + w)*T_ + l];
    float v1 = g_w[((size_t)ib*H_ + w)*T_ + l + 32];
    float mx = fmaxf(v0, v1);
    #pragma unroll
    for (int o = 16; o; o >>= 1) mx = fmaxf(mx, __shfl_xor_sync(~0u, mx, o));
    float e0 = expf(v0 - mx), e1 = expf(v1 - mx);
    float s = e0 + e1;
    #pragma unroll
    for (int o = 16; o; o >>= 1) s += __shfl_xor_sync(~0u, s, o);
    float inv = 1.0f / s;
    p[w][l]      = e0 * inv;
    p[w][l + 32] = e1 * inv;
    __syncthreads();

    #pragma unroll
    for (int c0 = 0; c0 < E_; c0 += 256) {
        int c = c0 + t;
        int hh = c >> 6, d = c & 63;
        float acc = 0.f;
        #pragma unroll 8
        for (int j = 0; j < T_; j++)
            acc += p[hh][j] * g_qkv[(size_t)(j*B_ + b) * (3*E_) + 2*E_ + hh*64 + d];
        g_attn[(size_t)ib * E_ + c] = acc;
    }
}

// ---------------- layernorm ----------------------------------------------------
__global__ __launch_bounds__(256) void ln_kernel(
    const float* __restrict__ in, const float* __restrict__ g,
    const float* __restrict__ b, float* __restrict__ out)
{
    int row = blockIdx.x;
    const float* r = in + (size_t)row * E_;
    int t = threadIdx.x;
    float v0 = r[t], v1 = r[t + 256];
    float s = v0 + v1, sq = v0*v0 + v1*v1;
    #pragma unroll
    for (int o = 16; o; o >>= 1) {
        s  += __shfl_xor_sync(~0u, s,  o);
        sq += __shfl_xor_sync(~0u, sq, o);
    }
    __shared__ float ss[8], ssq[8];
    int w = t >> 5, l = t & 31;
    if (l == 0) { ss[w] = s; ssq[w] = sq; }
    __syncthreads();
    if (w == 0) {
        s  = (l < 8) ? ss[l]  : 0.f;
        sq = (l < 8) ? ssq[l] : 0.f;
        #pragma unroll
        for (int o = 4; o; o >>= 1) {
            s  += __shfl_xor_sync(~0u, s,  o);
            sq += __shfl_xor_sync(~0u, sq, o);
        }
        if (l == 0) { ss[0] = s; ssq[0] = sq; }
    }
    __syncthreads();
    float mu   = ss[0]  * (1.f / E_);
    float var  = ssq[0] * (1.f / E_) - mu * mu;
    float rstd = rsqrtf(var + 1e-5f);
    out[(size_t)row*E_ + t]       = (v0 - mu) * rstd * g[t]       + b[t];
    out[(size_t)row*E_ + t + 256] = (v1 - mu) * rstd * g[t + 256] + b[t + 256];
}

// ---------------- launch --------------------------------------------------------
extern "C" void kernel_launch(void* const* d_in, const int* in_sizes, int n_in,
                              void* d_out, int out_size)
{
    const float* x        = (const float*)d_in[0];
    const float* relation = (const float*)d_in[1];
    const float* in_w     = (const float*)d_in[2];
    const float* in_b     = (const float*)d_in[3];
    const float* rel_w    = (const float*)d_in[4];
    const float* rel_b    = (const float*)d_in[5];
    const float* out_w    = (const float*)d_in[6];
    const float* out_b    = (const float*)d_in[7];
    const float* fc1_w    = (const float*)d_in[8];
    const float* fc1_b    = (const float*)d_in[9];
    const float* fc2_w    = (const float*)d_in[10];
    const float* fc2_b    = (const float*)d_in[11];
    const float* ln1_g    = (const float*)d_in[12];
    const float* ln1_b    = (const float*)d_in[13];
    const float* ln2_g    = (const float*)d_in[14];
    const float* ln2_b    = (const float*)d_in[15];
    float* out = (float*)d_out;

    const int SM_BT = (2*128*PA_ + 2*128*PA_) * 4;
    const int SM_BN = (2*128*PA_ + 2*32*PB_) * 4;

    static float *p_qkv = nullptr, *p_attn, *p_ao, *p_h, *p_f1, *p_f2;
    if (!p_qkv) {
        cudaGetSymbolAddress((void**)&p_qkv,  g_qkv);
        cudaGetSymbolAddress((void**)&p_attn, g_attn);
        cudaGetSymbolAddress((void**)&p_ao,   g_ao);
        cudaGetSymbolAddress((void**)&p_h,    g_h);
        cudaGetSymbolAddress((void**)&p_f1,   g_f1);
        cudaGetSymbolAddress((void**)&p_f2,   g_f2);
        cudaFuncSetAttribute(relw_mma, cudaFuncAttributeMaxDynamicSharedMemorySize, 98304);
        cudaFuncSetAttribute(gemm_tf32<true, 0>, cudaFuncAttributeMaxDynamicSharedMemorySize, SM_BT);
        cudaFuncSetAttribute(gemm_tf32<false, 1>, cudaFuncAttributeMaxDynamicSharedMemorySize, SM_BN);
        cudaFuncSetAttribute(gemm_tf32<false, 2>, cudaFuncAttributeMaxDynamicSharedMemorySize, SM_BN);
    }

    dim3 blk(256);

    // 0a. prepass: relation -> bf16 (134MB)
    cvt_rel<<<ROWS_ * E_ / (8 * 256), 256>>>(relation);
    // 0b. prepass: interleaved bf16 weight tiles [h][k][128]
    build_bw<<<1024, 256>>>(rel_w);

    // 1. qkv = x @ in_w^T + in_b    (tf32)
    gemm_tf32<true, 0><<<dim3(1536/128, TB_/128), blk, SM_BT>>>(x, in_w, in_b, nullptr, p_qkv, TB_, 3*E_, E_);

    // 2. relation GEMM (bf16 HMMA, 3-stage cp.async) + fused logits
    relw_mma<<<dim3(H_, ROWS_/128), blk, 98304>>>(rel_b);

    // 3. softmax + attn
    softmax_attn_kernel<<<TB_, 256>>>();

    // 4. out proj + residual       (tf32)
    gemm_tf32<false, 2><<<dim3(E_/128, TB_/128), blk, SM_BN>>>(p_attn, out_w, out_b, x, p_ao, TB_, E_, E_);

    // 5. LN1
    ln_kernel<<<TB_, 256>>>(p_ao, ln1_g, ln1_b, p_h);

    // 6. fc1 + relu                (tf32)
    gemm_tf32<false, 1><<<dim3(F_/128, TB_/128), blk, SM_BN>>>(p_h, fc1_w, fc1_b, nullptr, p_f1, TB_, F_, E_);

    // 7. fc2 + residual h          (tf32)
    gemm_tf32<false, 2><<<dim3(E_/128, TB_/128), blk, SM_BN>>>(p_f1, fc2_w, fc2_b, p_h, p_f2, TB_, E_, F_);

    // 8. LN2 -> out
    ln_kernel<<<TB_, 256>>>(p_f2, ln2_g, ln2_b, out);
}

// round 7
// speedup vs baseline: 5.4402x; 1.0535x over previous
#include <cuda_runtime.h>
#include <cuda_bf16.h>
#include <cstdint>

#define T_  64
#define B_  32
#define E_  512
#define H_  8
#define F_  2048
#define TB_ (T_*B_)        // 2048
#define ROWS_ (T_*T_*B_)   // 131072

// ---------------- scratch ----------------------------------------------------
__device__ float g_qkv[TB_ * 3 * E_];
__device__ float g_w[TB_ * H_ * T_];
__device__ float g_attn[TB_ * E_];
__device__ float g_ao[TB_ * E_];
__device__ float g_h[TB_ * E_];
__device__ float g_f1[TB_ * F_];
__device__ float g_f2[TB_ * E_];
__device__ __nv_bfloat16 g_arel[(size_t)ROWS_ * E_];   // relation in bf16 (134MB)
__device__ __nv_bfloat16 g_bw[H_ * E_ * 128];          // [h][k][2d interleaved ra/rb]

// ---------------- helpers ------------------------------------------------------
__device__ __forceinline__ uint32_t smem_u32(const void* p) {
    return (uint32_t)__cvta_generic_to_shared(p);
}
__device__ __forceinline__ void ldsm_x4(uint32_t& r0, uint32_t& r1, uint32_t& r2, uint32_t& r3, uint32_t a) {
    asm volatile("ldmatrix.sync.aligned.m8n8.x4.shared.b16 {%0,%1,%2,%3},[%4];"
                 : "=r"(r0), "=r"(r1), "=r"(r2), "=r"(r3) : "r"(a));
}
__device__ __forceinline__ void ldsm_x4_t(uint32_t& r0, uint32_t& r1, uint32_t& r2, uint32_t& r3, uint32_t a) {
    asm volatile("ldmatrix.sync.aligned.m8n8.x4.trans.shared.b16 {%0,%1,%2,%3},[%4];"
                 : "=r"(r0), "=r"(r1), "=r"(r2), "=r"(r3) : "r"(a));
}
__device__ __forceinline__ void mma16816(float* c, const uint32_t* a, const uint32_t* b) {
    asm volatile("mma.sync.aligned.m16n8k16.row.col.f32.bf16.bf16.f32 "
                 "{%0,%1,%2,%3},{%4,%5,%6,%7},{%8,%9},{%0,%1,%2,%3};"
                 : "+f"(c[0]), "+f"(c[1]), "+f"(c[2]), "+f"(c[3])
                 : "r"(a[0]), "r"(a[1]), "r"(a[2]), "r"(a[3]), "r"(b[0]), "r"(b[1]));
}
__device__ __forceinline__ void mma_tf32(float* c, const float* a, const float* b) {
    asm volatile("mma.sync.aligned.m16n8k8.row.col.f32.tf32.tf32.f32 "
                 "{%0,%1,%2,%3},{%4,%5,%6,%7},{%8,%9},{%0,%1,%2,%3};"
                 : "+f"(c[0]), "+f"(c[1]), "+f"(c[2]), "+f"(c[3])
                 : "r"(__float_as_uint(a[0])), "r"(__float_as_uint(a[1])),
                   "r"(__float_as_uint(a[2])), "r"(__float_as_uint(a[3])),
                   "r"(__float_as_uint(b[0])), "r"(__float_as_uint(b[1])));
}
__device__ __forceinline__ uint32_t f2bf2(float x, float y) {
    __nv_bfloat162 t = __floats2bfloat162_rn(x, y);
    return *reinterpret_cast<uint32_t*>(&t);
}
__device__ __forceinline__ float to_tf32(float x) {
    float y;
    asm("cvt.rna.tf32.f32 %0, %1;" : "=f"(y) : "f"(x));
    return y;
}
__device__ __forceinline__ float4 to_tf32_4(float4 v) {
    return make_float4(to_tf32(v.x), to_tf32(v.y), to_tf32(v.z), to_tf32(v.w));
}
#define CP_ASYNC16(saddr, gptr) \
    asm volatile("cp.async.cg.shared.global [%0], [%1], 16;" :: "r"(saddr), "l"(gptr) : "memory")
#define CP_COMMIT() asm volatile("cp.async.commit_group;" ::: "memory")
#define CP_WAIT1()  asm volatile("cp.async.wait_group 1;" ::: "memory")
#define CP_WAIT0()  asm volatile("cp.async.wait_group 0;" ::: "memory")

// ---------------- prepass: relation fp32 -> bf16 ------------------------------
__global__ __launch_bounds__(256) void cvt_rel(const float* __restrict__ rel)
{
    size_t i = ((size_t)blockIdx.x * 256 + threadIdx.x) * 8;
    float4 a = *(const float4*)(rel + i);
    float4 b = *(const float4*)(rel + i + 4);
    uint4 v = make_uint4(f2bf2(a.x, a.y), f2bf2(a.z, a.w),
                         f2bf2(b.x, b.y), f2bf2(b.z, b.w));
    *(uint4*)((char*)g_arel + i * 2) = v;
}

// ---------------- prepass: interleaved bf16 weight tiles [h][k][128] ----------
__global__ __launch_bounds__(256) void build_bw(const float* __restrict__ relw)
{
    int idx = blockIdx.x * 256 + threadIdx.x;    // 262144
    int d = idx & 63;
    int k = (idx >> 6) & 511;
    int h = idx >> 15;
    g_bw[((size_t)h*E_ + k) * 128 + 2*d    ] = __float2bfloat16(relw[(size_t)k*(2*E_) + h*64 + d]);
    g_bw[((size_t)h*E_ + k) * 128 + 2*d + 1] = __float2bfloat16(relw[(size_t)k*(2*E_) + E_ + h*64 + d]);
}

// ---------------- fused relation GEMM (bf16 HMMA, 3-stage cp.async) -----------
// CTA tile: 256 rows x 128 (one head). 8 warps, warp tile 64x64. K=512, 8 stages.
// Prefetch issued AFTER the stage barrier (3-buffer safety), one barrier/stage.
#define SA_STRIDE 32768
#define SB_STRIDE 16384
#define SB_BASE_  98304
#define RELW_SMEM 147456
__global__ void __launch_bounds__(256, 1) relw_mma(const float* __restrict__ relb)
{
    extern __shared__ char smem[];
    const uint32_t AsBase = smem_u32(smem);
    const uint32_t BsBase = AsBase + SB_BASE_;
    float* red = (float*)smem;

    const int h   = blockIdx.x;
    const int n0  = blockIdx.y * 256;
    const int tid = threadIdx.x;
    const int lane = tid & 31, warp = tid >> 5;
    const int warp_m = warp >> 1, warp_n = warp & 1;   // 4 x 2, warp tile 64x64

    float acc[4][8][4];
    #pragma unroll
    for (int i = 0; i < 4; i++)
        #pragma unroll
        for (int j = 0; j < 8; j++)
            #pragma unroll
            for (int k = 0; k < 4; k++) acc[i][j][k] = 0.f;

    const __nv_bfloat16* Ag = g_arel + (size_t)n0 * E_;
    const __nv_bfloat16* Bg = g_bw + (size_t)h * E_ * 128;

    auto load_stage = [&](int s, int buf) {
        uint32_t Ab = AsBase + buf * SA_STRIDE;
        #pragma unroll
        for (int c = 0; c < 8; c++) {
            int idx = c * 256 + tid;          // 2048 chunks of 16B (256 rows x 128B)
            int row = idx >> 3, cg = idx & 7;
            CP_ASYNC16(Ab + row*128 + (((cg ^ (row & 7)) << 4)),
                       Ag + (size_t)row * E_ + s*64 + cg*8);
        }
        uint32_t Bb = BsBase + buf * SB_STRIDE;
        #pragma unroll
        for (int c = 0; c < 4; c++) {
            int idx = c * 256 + tid;          // 1024 chunks (64 k-rows x 256B)
            int kr = idx >> 4, ng = idx & 15;
            CP_ASYNC16(Bb + kr*256 + (((ng ^ (kr & 7)) << 4)),
                       Bg + (size_t)(s*64 + kr) * 128 + ng*8);
        }
        CP_COMMIT();
    };

    load_stage(0, 0);
    load_stage(1, 1);

    const int a_r  = warp_m*64 + (lane & 15);          // +mi*16
    const int a_kc = (lane >> 4) << 3;                 // +ks*16
    const int b_kr = lane & 15;                        // +ks*16
    const int b_nc = warp_n*64 + ((lane >> 4) << 3);   // +g*16

    #pragma unroll
    for (int s = 0; s < 8; s++) {
        if (s < 7) CP_WAIT1(); else CP_WAIT0();
        __syncthreads();
        // safe: all warps have finished reading buf (s-1)%3 == (s+2)%3
        if (s < 6) load_stage(s + 2, (s + 2) % 3);

        const uint32_t Ab = AsBase + (s % 3) * SA_STRIDE;
        const uint32_t Bb = BsBase + (s % 3) * SB_STRIDE;

        #pragma unroll
        for (int ks = 0; ks < 4; ks++) {
            uint32_t a[4][4];
            #pragma unroll
            for (int mi = 0; mi < 4; mi++) {
                int r  = a_r + mi*16;
                int kc = a_kc + ks*16;
                ldsm_x4(a[mi][0], a[mi][1], a[mi][2], a[mi][3],
                        Ab + r*128 + ((((kc >> 3) ^ (r & 7)) << 4)));
            }
            uint32_t b[8][2];
            #pragma unroll
            for (int g = 0; g < 4; g++) {
                int krow = b_kr + ks*16;
                int ncol = b_nc + g*16;
                ldsm_x4_t(b[2*g][0], b[2*g][1], b[2*g+1][0], b[2*g+1][1],
                          Bb + krow*256 + ((((ncol >> 3) ^ (krow & 7)) << 4)));
            }
            #pragma unroll
            for (int mi = 0; mi < 4; mi++)
                #pragma unroll
                for (int nf = 0; nf < 8; nf++)
                    mma16816(acc[mi][nf], a[mi], b[nf]);
        }
    }

    // ---- fused epilogue: (c0 + bra + q) * (c1 + brb + k), reduce over d --------
    const int tig = lane & 3, grp = lane >> 2;
    float part[4][2] = {{0.f,0.f},{0.f,0.f},{0.f,0.f},{0.f,0.f}};
    #pragma unroll
    for (int nf = 0; nf < 8; nf++) {
        int d = warp_n*32 + nf*4 + tig;
        float bra = relb[h*64 + d];
        float brb = relb[E_ + h*64 + d];
        #pragma unroll
        for (int mi = 0; mi < 4; mi++)
            #pragma unroll
            for (int hf = 0; hf < 2; hf++) {
                int r  = warp_m*64 + mi*16 + grp + hf*8;
                int n  = n0 + r;
                int b  = n & 31;
                int ji = n >> 5;
                int ii = ji & 63, jj = ji >> 6;
                float q = g_qkv[(size_t)(ii*B_ + b) * (3*E_) + h*64 + d];
                float k = g_qkv[(size_t)(jj*B_ + b) * (3*E_) + E_ + h*64 + d];
                part[mi][hf] += (acc[mi][nf][hf*2+0] + bra + q) * (acc[mi][nf][hf*2+1] + brb + k);
            }
    }
    #pragma unroll
    for (int mi = 0; mi < 4; mi++)
        #pragma unroll
        for (int hf = 0; hf < 2; hf++) {
            float v = part[mi][hf];
            v += __shfl_xor_sync(~0u, v, 1);
            v += __shfl_xor_sync(~0u, v, 2);
            part[mi][hf] = v;
        }
    __syncthreads();   // mainloop smem dead; safe to alias red
    if (tig == 0) {
        #pragma unroll
        for (int mi = 0; mi < 4; mi++)
            #pragma unroll
            for (int hf = 0; hf < 2; hf++) {
                int r = warp_m*64 + mi*16 + grp + hf*8;
                red[r*2 + warp_n] = part[mi][hf];
            }
    }
    __syncthreads();
    {
        int n  = n0 + tid;                 // 256 rows, 256 threads
        int b  = n & 31;
        int ji = n >> 5;
        int ii = ji & 63, jj = ji >> 6;
        g_w[((size_t)(ii*B_ + b) * H_ + h) * T_ + jj] =
            (red[tid*2] + red[tid*2 + 1]) * 0.015625f;
    }
}

// ---------------- tf32 GEMM: 128x128 tile, K-stage 32, padded-scalar smem -----
#define PA_ 36
#define PB_ 136
template<bool BTRANS, int EPI>
__global__ __launch_bounds__(256) void gemm_tf32(
    const float* __restrict__ A, const float* __restrict__ Bm,
    const float* __restrict__ bias, const float* __restrict__ add,
    float* __restrict__ C, int M, int N, int K)
{
    extern __shared__ float sm[];
    const int AW = 128 * PA_;
    const int BW = BTRANS ? 128 * PA_ : 32 * PB_;
    float* Asm[2] = { sm, sm + AW };
    float* Bsm[2] = { sm + 2*AW, sm + 2*AW + BW };

    const int tid = threadIdx.x;
    const int lane = tid & 31, warp = tid >> 5;
    const int wm = warp >> 1, wn = warp & 1;
    const int grp = lane >> 2, tig = lane & 3;
    const int m0 = blockIdx.y * 128;
    const int n0 = blockIdx.x * 128;

    float acc[2][8][4];
    #pragma unroll
    for (int i = 0; i < 2; i++)
        #pragma unroll
        for (int j = 0; j < 8; j++)
            #pragma unroll
            for (int k = 0; k < 4; k++) acc[i][j][k] = 0.f;

    const int S = K >> 5;
    float4 pa[4], pb[4];

    #pragma unroll
    for (int it = 0; it < 4; it++) {
        int idx = it * 1024 + tid * 4;
        pa[it] = *(const float4*)(A + (size_t)(m0 + (idx >> 5)) * K + (idx & 31));
        if (BTRANS) pb[it] = *(const float4*)(Bm + (size_t)(n0 + (idx >> 5)) * K + (idx & 31));
        else        pb[it] = *(const float4*)(Bm + (size_t)(idx >> 7) * N + n0 + (idx & 127));
    }
    #pragma unroll
    for (int it = 0; it < 4; it++) {
        int idx = it * 1024 + tid * 4;
        *(float4*)&Asm[0][(idx >> 5) * PA_ + (idx & 31)] = to_tf32_4(pa[it]);
        if (BTRANS) *(float4*)&Bsm[0][(idx >> 5) * PA_ + (idx & 31)] = to_tf32_4(pb[it]);
        else        *(float4*)&Bsm[0][(idx >> 7) * PB_ + (idx & 127)] = to_tf32_4(pb[it]);
    }
    __syncthreads();

    for (int s = 0; s < S; s++) {
        if (s < S - 1) {
            int k0 = (s + 1) * 32;
            #pragma unroll
            for (int it = 0; it < 4; it++) {
                int idx = it * 1024 + tid * 4;
                pa[it] = *(const float4*)(A + (size_t)(m0 + (idx >> 5)) * K + k0 + (idx & 31));
                if (BTRANS) pb[it] = *(const float4*)(Bm + (size_t)(n0 + (idx >> 5)) * K + k0 + (idx & 31));
                else        pb[it] = *(const float4*)(Bm + (size_t)(k0 + (idx >> 7)) * N + n0 + (idx & 127));
            }
        }
        const float* Ab = Asm[s & 1];
        const float* Bb = Bsm[s & 1];
        #pragma unroll
        for (int ks = 0; ks < 4; ks++) {
            float a[2][4];
            #pragma unroll
            for (int mi = 0; mi < 2; mi++) {
                int r = wm*32 + mi*16 + grp;
                int c = ks*8 + tig;
                a[mi][0] = Ab[r * PA_ + c];
                a[mi][1] = Ab[(r + 8) * PA_ + c];
                a[mi][2] = Ab[r * PA_ + c + 4];
                a[mi][3] = Ab[(r + 8) * PA_ + c + 4];
            }
            float b[8][2];
            #pragma unroll
            for (int nf = 0; nf < 8; nf++) {
                int n = wn*64 + nf*8 + grp;
                if (BTRANS) {
                    b[nf][0] = Bb[n * PA_ + ks*8 + tig];
                    b[nf][1] = Bb[n * PA_ + ks*8 + tig + 4];
                } else {
                    b[nf][0] = Bb[(ks*8 + tig) * PB_ + n];
                    b[nf][1] = Bb[(ks*8 + tig + 4) * PB_ + n];
                }
            }
            #pragma unroll
            for (int mi = 0; mi < 2; mi++)
                #pragma unroll
                for (int nf = 0; nf < 8; nf++)
                    mma_tf32(acc[mi][nf], a[mi], b[nf]);
        }
        if (s < S - 1) {
            __syncthreads();
            float* Ac = Asm[(s + 1) & 1];
            float* Bc = Bsm[(s + 1) & 1];
            #pragma unroll
            for (int it = 0; it < 4; it++) {
                int idx = it * 1024 + tid * 4;
                *(float4*)&Ac[(idx >> 5) * PA_ + (idx & 31)] = to_tf32_4(pa[it]);
                if (BTRANS) *(float4*)&Bc[(idx >> 5) * PA_ + (idx & 31)] = to_tf32_4(pb[it]);
                else        *(float4*)&Bc[(idx >> 7) * PB_ + (idx & 127)] = to_tf32_4(pb[it]);
            }
            __syncthreads();
        }
    }

    #pragma unroll
    for (int mi = 0; mi < 2; mi++)
        #pragma unroll
        for (int hf = 0; hf < 2; hf++) {
            int row = m0 + wm*32 + mi*16 + grp + hf*8;
            #pragma unroll
            for (int nf = 0; nf < 8; nf++) {
                int col = n0 + wn*64 + nf*8 + tig*2;
                float v0 = acc[mi][nf][hf*2 + 0] + bias[col];
                float v1 = acc[mi][nf][hf*2 + 1] + bias[col + 1];
                if (EPI == 1) { v0 = fmaxf(v0, 0.f); v1 = fmaxf(v1, 0.f); }
                if (EPI == 2) {
                    v0 += add[(size_t)row * N + col];
                    v1 += add[(size_t)row * N + col + 1];
                }
                *(float2*)(C + (size_t)row * N + col) = make_float2(v0, v1);
            }
        }
}

// ---------------- softmax over j + attn = p @ v ------------------------------
__global__ __launch_bounds__(256) void softmax_attn_kernel()
{
    int ib = blockIdx.x;
    int b  = ib & 31;
    __shared__ float p[H_][T_];
    int t = threadIdx.x;
    int w = t >> 5, l = t & 31;

    float v0 = g_w[((size_t)ib*H_ + w)*T_ + l];
    float v1 = g_w[((size_t)ib*H_ + w)*T_ + l + 32];
    float mx = fmaxf(v0, v1);
    #pragma unroll
    for (int o = 16; o; o >>= 1) mx = fmaxf(mx, __shfl_xor_sync(~0u, mx, o));
    float e0 = expf(v0 - mx), e1 = expf(v1 - mx);
    float s = e0 + e1;
    #pragma unroll
    for (int o = 16; o; o >>= 1) s += __shfl_xor_sync(~0u, s, o);
    float inv = 1.0f / s;
    p[w][l]      = e0 * inv;
    p[w][l + 32] = e1 * inv;
    __syncthreads();

    #pragma unroll
    for (int c0 = 0; c0 < E_; c0 += 256) {
        int c = c0 + t;
        int hh = c >> 6, d = c & 63;
        float acc = 0.f;
        #pragma unroll 8
        for (int j = 0; j < T_; j++)
            acc += p[hh][j] * g_qkv[(size_t)(j*B_ + b) * (3*E_) + 2*E_ + hh*64 + d];
        g_attn[(size_t)ib * E_ + c] = acc;
    }
}

// ---------------- layernorm ----------------------------------------------------
__global__ __launch_bounds__(256) void ln_kernel(
    const float* __restrict__ in, const float* __restrict__ g,
    const float* __restrict__ b, float* __restrict__ out)
{
    int row = blockIdx.x;
    const float* r = in + (size_t)row * E_;
    int t = threadIdx.x;
    float v0 = r[t], v1 = r[t + 256];
    float s = v0 + v1, sq = v0*v0 + v1*v1;
    #pragma unroll
    for (int o = 16; o; o >>= 1) {
        s  += __shfl_xor_sync(~0u, s,  o);
        sq += __shfl_xor_sync(~0u, sq, o);
    }
    __shared__ float ss[8], ssq[8];
    int w = t >> 5, l = t & 31;
    if (l == 0) { ss[w] = s; ssq[w] = sq; }
    __syncthreads();
    if (w == 0) {
        s  = (l < 8) ? ss[l]  : 0.f;
        sq = (l < 8) ? ssq[l] : 0.f;
        #pragma unroll
        for (int o = 4; o; o >>= 1) {
            s  += __shfl_xor_sync(~0u, s,  o);
            sq += __shfl_xor_sync(~0u, sq, o);
        }
        if (l == 0) { ss[0] = s; ssq[0] = sq; }
    }
    __syncthreads();
    float mu   = ss[0]  * (1.f / E_);
    float var  = ssq[0] * (1.f / E_) - mu * mu;
    float rstd = rsqrtf(var + 1e-5f);
    out[(size_t)row*E_ + t]       = (v0 - mu) * rstd * g[t]       + b[t];
    out[(size_t)row*E_ + t + 256] = (v1 - mu) * rstd * g[t + 256] + b[t + 256];
}

// ---------------- launch --------------------------------------------------------
extern "C" void kernel_launch(void* const* d_in, const int* in_sizes, int n_in,
                              void* d_out, int out_size)
{
    const float* x        = (const float*)d_in[0];
    const float* relation = (const float*)d_in[1];
    const float* in_w     = (const float*)d_in[2];
    const float* in_b     = (const float*)d_in[3];
    const float* rel_w    = (const float*)d_in[4];
    const float* rel_b    = (const float*)d_in[5];
    const float* out_w    = (const float*)d_in[6];
    const float* out_b    = (const float*)d_in[7];
    const float* fc1_w    = (const float*)d_in[8];
    const float* fc1_b    = (const float*)d_in[9];
    const float* fc2_w    = (const float*)d_in[10];
    const float* fc2_b    = (const float*)d_in[11];
    const float* ln1_g    = (const float*)d_in[12];
    const float* ln1_b    = (const float*)d_in[13];
    const float* ln2_g    = (const float*)d_in[14];
    const float* ln2_b    = (const float*)d_in[15];
    float* out = (float*)d_out;

    const int SM_BT = (2*128*PA_ + 2*128*PA_) * 4;
    const int SM_BN = (2*128*PA_ + 2*32*PB_) * 4;

    static float *p_qkv = nullptr, *p_attn, *p_ao, *p_h, *p_f1, *p_f2;
    if (!p_qkv) {
        cudaGetSymbolAddress((void**)&p_qkv,  g_qkv);
        cudaGetSymbolAddress((void**)&p_attn, g_attn);
        cudaGetSymbolAddress((void**)&p_ao,   g_ao);
        cudaGetSymbolAddress((void**)&p_h,    g_h);
        cudaGetSymbolAddress((void**)&p_f1,   g_f1);
        cudaGetSymbolAddress((void**)&p_f2,   g_f2);
        cudaFuncSetAttribute(relw_mma, cudaFuncAttributeMaxDynamicSharedMemorySize, RELW_SMEM);
        cudaFuncSetAttribute(gemm_tf32<true, 0>, cudaFuncAttributeMaxDynamicSharedMemorySize, SM_BT);
        cudaFuncSetAttribute(gemm_tf32<false, 1>, cudaFuncAttributeMaxDynamicSharedMemorySize, SM_BN);
        cudaFuncSetAttribute(gemm_tf32<false, 2>, cudaFuncAttributeMaxDynamicSharedMemorySize, SM_BN);
    }

    dim3 blk(256);

    // 0a. prepass: relation -> bf16 (134MB)
    cvt_rel<<<ROWS_ * E_ / (8 * 256), 256>>>(relation);
    // 0b. prepass: interleaved bf16 weight tiles [h][k][128]
    build_bw<<<1024, 256>>>(rel_w);

    // 1. qkv = x @ in_w^T + in_b    (tf32)
    gemm_tf32<true, 0><<<dim3(1536/128, TB_/128), blk, SM_BT>>>(x, in_w, in_b, nullptr, p_qkv, TB_, 3*E_, E_);

    // 2. relation GEMM (bf16 HMMA, 256x128 tile, 3-stage cp.async) + fused logits
    relw_mma<<<dim3(H_, ROWS_/256), blk, RELW_SMEM>>>(rel_b);

    // 3. softmax + attn
    softmax_attn_kernel<<<TB_, 256>>>();

    // 4. out proj + residual       (tf32)
    gemm_tf32<false, 2><<<dim3(E_/128, TB_/128), blk, SM_BN>>>(p_attn, out_w, out_b, x, p_ao, TB_, E_, E_);

    // 5. LN1
    ln_kernel<<<TB_, 256>>>(p_ao, ln1_g, ln1_b, p_h);

    // 6. fc1 + relu                (tf32)
    gemm_tf32<false, 1><<<dim3(F_/128, TB_/128), blk, SM_BN>>>(p_h, fc1_w, fc1_b, nullptr, p_f1, TB_, F_, E_);

    // 7. fc2 + residual h          (tf32)
    gemm_tf32<false, 2><<<dim3(E_/128, TB_/128), blk, SM_BN>>>(p_f1, fc2_w, fc2_b, p_h, p_f2, TB_, E_, F_);

    // 8. LN2 -> out
    ln_kernel<<<TB_, 256>>>(p_f2, ln2_g, ln2_b, out);
}